// round 10
// baseline (speedup 1.0000x reference)
#include <cuda_runtime.h>
#include <cuda_bf16.h>
#include <math.h>
#include <cstdint>

#define NN 40000
#define EE 1280000
#define ETOT (EE + NN)
#define DD 256
#define BB 64
#define NCLS 20
#define KBIG 5000
#define KPBIG 5024   /* 157 * 32 */
#define SCB 157      /* ceil(NN/256) scan blocks */

// ---------------- scratch (static device allocations) ----------------------
__device__ float g_x0[NN * DD];
__device__ float g_x1[NN * DD];
__device__ float g_h[NN * DD];
__device__ float g_ssrc[NN * 8];
__device__ float g_sdst[NN * 8];
__device__ int   g_deg[NN];
__device__ int   g_off[NN + 1];
__device__ int   g_pos[NN];
__device__ int   g_csr[ETOT];
__device__ int   g_bsum[256];
__device__ float g_p2[BB * DD];
__device__ float g_p0[BB * DD];
__device__ float g_cnt[BB];
__device__ __nv_bfloat16 g_wbt_hi[256 * KPBIG];
__device__ __nv_bfloat16 g_wbt_lo[256 * KPBIG];
__device__ __nv_bfloat16 g_w1t_hi[256 * 256];
__device__ __nv_bfloat16 g_w1t_lo[256 * 256];
__device__ __nv_bfloat16 g_w2t_hi[256 * 256];
__device__ __nv_bfloat16 g_w2t_lo[256 * 256];

__device__ __forceinline__ uint32_t bf2pack(float a, float b) {
    __nv_bfloat162 t;
    t.x = __float2bfloat16(a);
    t.y = __float2bfloat16(b);
    return *reinterpret_cast<uint32_t*>(&t);
}

__device__ __forceinline__ void mma16816(float* c, const uint32_t* a, const uint32_t* b) {
    asm volatile(
        "mma.sync.aligned.m16n8k16.row.col.f32.bf16.bf16.f32 "
        "{%0,%1,%2,%3}, {%4,%5,%6,%7}, {%8,%9}, {%0,%1,%2,%3};"
        : "+f"(c[0]), "+f"(c[1]), "+f"(c[2]), "+f"(c[3])
        : "r"(a[0]), "r"(a[1]), "r"(a[2]), "r"(a[3]), "r"(b[0]), "r"(b[1]));
}

// ------- weight prep (coalesced transpose): W[K,256] -> Wt[256,KP] hi/lo ----
__global__ void wprep_kernel(const float* __restrict__ W,
                             __nv_bfloat16* __restrict__ th,
                             __nv_bfloat16* __restrict__ tl, int K, int KP)
{
    __shared__ float tile[32][33];
    const int kb = blockIdx.x * 32, nb = blockIdx.y * 32;
    const int tx = threadIdx.x & 31, ty = threadIdx.x >> 5;
#pragma unroll
    for (int r = ty; r < 32; r += 8) {
        int k = kb + r;
        tile[r][tx] = (k < K) ? __ldg(&W[(size_t)k * 256 + nb + tx]) : 0.f;
    }
    __syncthreads();
#pragma unroll
    for (int r = ty; r < 32; r += 8) {
        int n = nb + r, k = kb + tx;
        float v = tile[tx][r];
        __nv_bfloat16 h = __float2bfloat16(v);
        th[(size_t)n * KP + k] = h;
        tl[(size_t)n * KP + k] = __float2bfloat16(v - __bfloat162float(h));
    }
}

// ---------------- mma.sync GEMM (proven R3 shape) ---------------------------
#define KROWB 80
#define ABUF_H 0
#define ABUF_L (128 * KROWB)
#define BBUF_H (2 * 128 * KROWB)
#define BBUF_L (3 * 128 * KROWB)
#define BUFSZ  (4 * 128 * KROWB)
#define MM_SMEM (2 * BUFSZ)

__global__ void __launch_bounds__(256, 1)
mm_mma_kernel(const float* __restrict__ A,
              const __nv_bfloat16* __restrict__ Bh,
              const __nv_bfloat16* __restrict__ Bl,
              const float* __restrict__ bias,
              float* __restrict__ C, int M, int Kdim, int KP)
{
    extern __shared__ char smem[];
    const int tid = threadIdx.x, wid = tid >> 5, lane = tid & 31;
    const int group = lane >> 2, tig = lane & 3;
    const int rg = wid >> 2, cg = wid & 3;
    const int r0 = blockIdx.x * 128, n0 = blockIdx.y * 128;

    float acc[4][4][4];
#pragma unroll
    for (int mt = 0; mt < 4; mt++)
#pragma unroll
        for (int nt = 0; nt < 4; nt++)
#pragma unroll
            for (int j = 0; j < 4; j++) acc[mt][nt][j] = 0.f;

    const int NCH = KP >> 5;
    const int arow = tid >> 1;
    const int acol0 = (tid & 1) * 16;
    const bool arok = (r0 + arow) < M;
    const float* Abase = A + (size_t)(r0 + arow) * Kdim;

    float apf[16];
    uint4 bpfh[2], bpfl[2];

#define LDG_CHUNK(K0) do {                                                   \
    _Pragma("unroll")                                                        \
    for (int ii = 0; ii < 4; ii++) {                                         \
        int c = (K0) + acol0 + ii * 4;                                       \
        float4 v = make_float4(0.f, 0.f, 0.f, 0.f);                          \
        if (arok) {                                                          \
            if (c + 3 < Kdim) v = *(const float4*)(Abase + c);               \
            else {                                                           \
                if (c     < Kdim) v.x = Abase[c];                            \
                if (c + 1 < Kdim) v.y = Abase[c + 1];                        \
                if (c + 2 < Kdim) v.z = Abase[c + 2];                        \
                if (c + 3 < Kdim) v.w = Abase[c + 3];                        \
            }                                                                \
        }                                                                    \
        apf[ii*4+0] = v.x; apf[ii*4+1] = v.y;                                \
        apf[ii*4+2] = v.z; apf[ii*4+3] = v.w;                                \
    }                                                                        \
    _Pragma("unroll")                                                        \
    for (int q = 0; q < 2; q++) {                                            \
        int idx = tid * 2 + q;                                               \
        int n = idx >> 2, seg = idx & 3;                                     \
        size_t so = (size_t)(n0 + n) * KP + (K0) + seg * 8;                  \
        bpfh[q] = *(const uint4*)(Bh + so);                                  \
        bpfl[q] = *(const uint4*)(Bl + so);                                  \
    }                                                                        \
} while (0)

    LDG_CHUNK(0);

    for (int i = 0; i < NCH; i++) {
        char* buf = smem + (size_t)(i & 1) * BUFSZ;

        {
            uint32_t ph[8], pl[8];
#pragma unroll
            for (int j = 0; j < 8; j++) {
                float vx = apf[2 * j], vy = apf[2 * j + 1];
                float hx = __bfloat162float(__float2bfloat16(vx));
                float hy = __bfloat162float(__float2bfloat16(vy));
                ph[j] = bf2pack(vx, vy);
                pl[j] = bf2pack(vx - hx, vy - hy);
            }
            uint32_t aoff = arow * KROWB + acol0 * 2;
            *(uint4*)(buf + ABUF_H + aoff)      = make_uint4(ph[0], ph[1], ph[2], ph[3]);
            *(uint4*)(buf + ABUF_H + aoff + 16) = make_uint4(ph[4], ph[5], ph[6], ph[7]);
            *(uint4*)(buf + ABUF_L + aoff)      = make_uint4(pl[0], pl[1], pl[2], pl[3]);
            *(uint4*)(buf + ABUF_L + aoff + 16) = make_uint4(pl[4], pl[5], pl[6], pl[7]);
#pragma unroll
            for (int q = 0; q < 2; q++) {
                int idx = tid * 2 + q;
                int n = idx >> 2, seg = idx & 3;
                uint32_t boff = n * KROWB + seg * 16;
                *(uint4*)(buf + BBUF_H + boff) = bpfh[q];
                *(uint4*)(buf + BBUF_L + boff) = bpfl[q];
            }
        }
        __syncthreads();

        if (i + 1 < NCH) LDG_CHUNK((i + 1) << 5);

#pragma unroll
        for (int ks = 0; ks < 2; ks++) {
            const uint32_t kb = (uint32_t)(ks * 16 + tig * 2) * 2;
            uint32_t ah[4][4], bhf[4][2], blf[4][2], alf[4][4];
#pragma unroll
            for (int mt = 0; mt < 4; mt++) {
                uint32_t rb = (uint32_t)(rg * 64 + mt * 16 + group) * KROWB;
                ah[mt][0] = *(const uint32_t*)(buf + ABUF_H + rb + kb);
                ah[mt][1] = *(const uint32_t*)(buf + ABUF_H + rb + 8 * KROWB + kb);
                ah[mt][2] = *(const uint32_t*)(buf + ABUF_H + rb + kb + 16);
                ah[mt][3] = *(const uint32_t*)(buf + ABUF_H + rb + 8 * KROWB + kb + 16);
            }
#pragma unroll
            for (int nt = 0; nt < 4; nt++) {
                uint32_t nb = (uint32_t)(cg * 32 + nt * 8 + group) * KROWB;
                bhf[nt][0] = *(const uint32_t*)(buf + BBUF_H + nb + kb);
                bhf[nt][1] = *(const uint32_t*)(buf + BBUF_H + nb + kb + 16);
            }
#pragma unroll
            for (int mt = 0; mt < 4; mt++)
#pragma unroll
                for (int nt = 0; nt < 4; nt++)
                    mma16816(acc[mt][nt], ah[mt], bhf[nt]);
#pragma unroll
            for (int nt = 0; nt < 4; nt++) {
                uint32_t nb = (uint32_t)(cg * 32 + nt * 8 + group) * KROWB;
                blf[nt][0] = *(const uint32_t*)(buf + BBUF_L + nb + kb);
                blf[nt][1] = *(const uint32_t*)(buf + BBUF_L + nb + kb + 16);
            }
#pragma unroll
            for (int mt = 0; mt < 4; mt++)
#pragma unroll
                for (int nt = 0; nt < 4; nt++)
                    mma16816(acc[mt][nt], ah[mt], blf[nt]);
#pragma unroll
            for (int mt = 0; mt < 4; mt++) {
                uint32_t rb = (uint32_t)(rg * 64 + mt * 16 + group) * KROWB;
                alf[mt][0] = *(const uint32_t*)(buf + ABUF_L + rb + kb);
                alf[mt][1] = *(const uint32_t*)(buf + ABUF_L + rb + 8 * KROWB + kb);
                alf[mt][2] = *(const uint32_t*)(buf + ABUF_L + rb + kb + 16);
                alf[mt][3] = *(const uint32_t*)(buf + ABUF_L + rb + 8 * KROWB + kb + 16);
            }
#pragma unroll
            for (int mt = 0; mt < 4; mt++)
#pragma unroll
                for (int nt = 0; nt < 4; nt++)
                    mma16816(acc[mt][nt], alf[mt], bhf[nt]);
        }
    }

#pragma unroll
    for (int nt = 0; nt < 4; nt++) {
        int c = n0 + cg * 32 + nt * 8 + tig * 2;
        float b0v = bias ? __ldg(bias + c) : 0.f;
        float b1v = bias ? __ldg(bias + c + 1) : 0.f;
#pragma unroll
        for (int mt = 0; mt < 4; mt++) {
            int r = r0 + rg * 64 + mt * 16 + group;
            if (r < M)
                *(float2*)(C + (size_t)r * 256 + c) =
                    make_float2(acc[mt][nt][0] + b0v, acc[mt][nt][1] + b1v);
            if (r + 8 < M)
                *(float2*)(C + (size_t)(r + 8) * 256 + c) =
                    make_float2(acc[mt][nt][2] + b0v, acc[mt][nt][3] + b1v);
        }
    }
#undef LDG_CHUNK
}

// ---------------- CSR build ------------------------------------------------
__global__ void deg_init_kernel(int* deg) {
    int i = blockIdx.x * blockDim.x + threadIdx.x;
    if (i < NN) deg[i] = 1;
}
__global__ void deg_count_kernel(const int* __restrict__ ei, int* deg) {
    int i = blockIdx.x * blockDim.x + threadIdx.x;
    if (i < EE) atomicAdd(&deg[ei[EE + i]], 1);
}

// --- 3-kernel coalesced scan ---
__global__ void scan_sum_kernel(const int* __restrict__ deg, int* __restrict__ bsum) {
    int i = blockIdx.x * 256 + threadIdx.x;
    int lane = threadIdx.x & 31, wid = threadIdx.x >> 5;
    int d = (i < NN) ? deg[i] : 0;
#pragma unroll
    for (int o = 16; o > 0; o >>= 1) d += __shfl_xor_sync(0xffffffffu, d, o);
    __shared__ int ws[8];
    if (lane == 0) ws[wid] = d;
    __syncthreads();
    if (threadIdx.x == 0) {
        int s = 0;
#pragma unroll
        for (int w = 0; w < 8; w++) s += ws[w];
        bsum[blockIdx.x] = s;
    }
}
__global__ void scan_top_kernel(int* __restrict__ bsum, int* __restrict__ off) {
    int t = threadIdx.x, lane = t & 31, wid = t >> 5;
    int v = (t < SCB) ? bsum[t] : 0;
    int x = v;
#pragma unroll
    for (int o = 1; o < 32; o <<= 1) {
        int y = __shfl_up_sync(0xffffffffu, x, o);
        if (lane >= o) x += y;
    }
    __shared__ int ws[8];
    if (lane == 31) ws[wid] = x;
    __syncthreads();
    int wpre = 0;
#pragma unroll
    for (int w = 0; w < 8; w++) if (w < wid) wpre += ws[w];
    int incl = x + wpre;
    if (t < SCB) bsum[t] = incl - v;        // exclusive
    if (t == 255) off[NN] = incl;            // total = ETOT
}
__global__ void scan_final_kernel(const int* __restrict__ deg,
                                  const int* __restrict__ bsum,
                                  int* __restrict__ off, int* __restrict__ pos) {
    int i = blockIdx.x * 256 + threadIdx.x;
    int lane = threadIdx.x & 31, wid = threadIdx.x >> 5;
    int d = (i < NN) ? deg[i] : 0;
    int x = d;
#pragma unroll
    for (int o = 1; o < 32; o <<= 1) {
        int y = __shfl_up_sync(0xffffffffu, x, o);
        if (lane >= o) x += y;
    }
    __shared__ int ws[8];
    if (lane == 31) ws[wid] = x;
    __syncthreads();
    int wpre = 0;
#pragma unroll
    for (int w = 0; w < 8; w++) if (w < wid) wpre += ws[w];
    int excl = x - d + wpre + bsum[blockIdx.x];
    if (i < NN) { off[i] = excl; pos[i] = excl; }
}

__global__ void csr_fill_kernel(const int* __restrict__ ei, int* pos, int* csr) {
    int i = blockIdx.x * blockDim.x + threadIdx.x;
    if (i >= ETOT) return;
    int s, d;
    if (i < EE) { s = ei[i]; d = ei[EE + i]; }
    else        { s = d = i - EE; }
    int p = atomicAdd(&pos[d], 1);
    csr[p] = s;
}

// ---------------- attention scores ----------------------------------------
template <int H, int C>
__global__ void scores_kernel(const float* __restrict__ h,
                              const float* __restrict__ asrc,
                              const float* __restrict__ adst,
                              float* __restrict__ ssrc, float* __restrict__ sdst)
{
    int gw = (blockIdx.x * blockDim.x + threadIdx.x) >> 5;
    if (gw >= NN) return;
    int lane = threadIdx.x & 31;

    const float4* hp = (const float4*)(h + gw * 256 + lane * 8);
    float4 v0 = hp[0], v1 = hp[1];
    const float4* ap = (const float4*)(asrc + lane * 8);
    float4 a0 = ap[0], a1 = ap[1];
    const float4* dp = (const float4*)(adst + lane * 8);
    float4 d0 = dp[0], d1 = dp[1];

    float ps = v0.x * a0.x + v0.y * a0.y + v0.z * a0.z + v0.w * a0.w +
               v1.x * a1.x + v1.y * a1.y + v1.z * a1.z + v1.w * a1.w;
    float pd = v0.x * d0.x + v0.y * d0.y + v0.z * d0.z + v0.w * d0.w +
               v1.x * d1.x + v1.y * d1.y + v1.z * d1.z + v1.w * d1.w;

    const int GC = C / 8;
#pragma unroll
    for (int o = 1; o < GC; o <<= 1) {
        ps += __shfl_xor_sync(0xffffffffu, ps, o);
        pd += __shfl_xor_sync(0xffffffffu, pd, o);
    }
    int myh = lane / GC;
    if ((lane & (GC - 1)) == 0) {
        ssrc[gw * H + myh] = ps;
        sdst[gw * H + myh] = pd;
    }
}

// ------- GAT aggregation fused with bias+elu+residual+LN (+ pooling) -------
template <int H, int C, bool POOL>
__global__ void agg_fused_kernel(const float* __restrict__ ssrc,
                                 const float* __restrict__ sdst,
                                 const float* __restrict__ h,
                                 const int* __restrict__ off,
                                 const int* __restrict__ csr,
                                 const float* __restrict__ bias,
                                 const float* __restrict__ xin,
                                 const float* __restrict__ g,
                                 const float* __restrict__ be,
                                 float* __restrict__ xout,
                                 const float* __restrict__ x0p,
                                 const int* __restrict__ batch,
                                 float* __restrict__ p2,
                                 float* __restrict__ p0,
                                 float* __restrict__ cnt)
{
    int gw = (blockIdx.x * blockDim.x + threadIdx.x) >> 5;
    if (gw >= NN) return;
    int lane = threadIdx.x & 31;

    int e0 = off[gw];
    int deg = off[gw + 1] - e0;

    const int ES = 32 / H;
    int hh = lane % H;
    int j0 = lane / H;

    float sd = __ldg(&sdst[gw * H + hh]);
    float m = -1e30f, z = 0.f;
    for (int j = j0; j < deg; j += ES) {
        int s = __ldg(&csr[e0 + j]);
        float e = __ldg(&ssrc[s * H + hh]) + sd;
        e = e > 0.f ? e : 0.2f * e;
        float mn = fmaxf(m, e);
        z = z * __expf(m - mn) + __expf(e - mn);
        m = mn;
    }
#pragma unroll
    for (int o = H; o < 32; o <<= 1) {
        float mo = __shfl_xor_sync(0xffffffffu, m, o);
        float zo = __shfl_xor_sync(0xffffffffu, z, o);
        float mn = fmaxf(m, mo);
        z = z * __expf(m - mn) + zo * __expf(mo - mn);
        m = mn;
    }

    const int myh = (lane * 8) / C;
    float my_m  = __shfl_sync(0xffffffffu, m, myh);
    float my_zi = 1.f / __shfl_sync(0xffffffffu, z, myh);
    float my_sd = __ldg(&sdst[gw * H + myh]);

    float acc[8] = {0.f, 0.f, 0.f, 0.f, 0.f, 0.f, 0.f, 0.f};
    for (int j = 0; j < deg; j++) {
        int s = __ldg(&csr[e0 + j]);
        float e = __ldg(&ssrc[s * H + myh]) + my_sd;
        e = e > 0.f ? e : 0.2f * e;
        float a = __expf(e - my_m) * my_zi;
        const float4* hp = (const float4*)(h + s * 256 + lane * 8);
        float4 v0 = __ldg(hp);
        float4 v1 = __ldg(hp + 1);
        acc[0] += a * v0.x; acc[1] += a * v0.y; acc[2] += a * v0.z; acc[3] += a * v0.w;
        acc[4] += a * v1.x; acc[5] += a * v1.y; acc[6] += a * v1.z; acc[7] += a * v1.w;
    }

    int base = gw * 256 + lane * 8;
    float4 b0 = *(const float4*)(bias + lane * 8);
    float4 b1 = *(const float4*)(bias + lane * 8 + 4);
    float4 x0v = *(const float4*)(xin + base);
    float4 x1v = *(const float4*)(xin + base + 4);
    float bb[8] = {b0.x, b0.y, b0.z, b0.w, b1.x, b1.y, b1.z, b1.w};
    float xv[8] = {x0v.x, x0v.y, x0v.z, x0v.w, x1v.x, x1v.y, x1v.z, x1v.w};

    float v[8];
    float sum = 0.f, sq = 0.f;
#pragma unroll
    for (int k = 0; k < 8; k++) {
        float t = acc[k] + bb[k];
        t = (t > 0.f) ? t : (__expf(t) - 1.f);
        t += xv[k];
        v[k] = t;
        sum += t;
        sq += t * t;
    }
#pragma unroll
    for (int o = 1; o < 32; o <<= 1) {
        sum += __shfl_xor_sync(0xffffffffu, sum, o);
        sq  += __shfl_xor_sync(0xffffffffu, sq, o);
    }
    float mean = sum * (1.f / 256.f);
    float var  = sq * (1.f / 256.f) - mean * mean;
    float rs   = rsqrtf(var + 1e-5f);

    float4 g0 = *(const float4*)(g + lane * 8);
    float4 g1 = *(const float4*)(g + lane * 8 + 4);
    float4 e0v = *(const float4*)(be + lane * 8);
    float4 e1v = *(const float4*)(be + lane * 8 + 4);
    float gv[8] = {g0.x, g0.y, g0.z, g0.w, g1.x, g1.y, g1.z, g1.w};
    float ev[8] = {e0v.x, e0v.y, e0v.z, e0v.w, e1v.x, e1v.y, e1v.z, e1v.w};

    float o0[8];
#pragma unroll
    for (int k = 0; k < 8; k++) o0[k] = (v[k] - mean) * rs * gv[k] + ev[k];

    if (!POOL) {
        *(float4*)(xout + base)     = make_float4(o0[0], o0[1], o0[2], o0[3]);
        *(float4*)(xout + base + 4) = make_float4(o0[4], o0[5], o0[6], o0[7]);
    } else {
        int b = __ldg(&batch[gw]);
        float* pp2 = p2 + b * 256 + lane * 8;
        float* pp0 = p0 + b * 256 + lane * 8;
        float4 z0 = *(const float4*)(x0p + base);
        float4 z1 = *(const float4*)(x0p + base + 4);
        float zv[8] = {z0.x, z0.y, z0.z, z0.w, z1.x, z1.y, z1.z, z1.w};
#pragma unroll
        for (int k = 0; k < 8; k++) {
            atomicAdd(pp2 + k, o0[k]);
            atomicAdd(pp0 + k, zv[k]);
        }
        if (lane == 0) atomicAdd(&cnt[b], 1.f);
    }
}

// ---------------- pooling init ---------------------------------------------
__global__ void pool_init_kernel(float* p2, float* p0, float* cnt) {
    int i = blockIdx.x * blockDim.x + threadIdx.x;
    if (i < BB * DD) { p2[i] = 0.f; p0[i] = 0.f; }
    if (i < BB) cnt[i] = 0.f;
}

// ---------------- classification head (block per graph) -------------------
__global__ void head_kernel(const float* __restrict__ p2,
                            const float* __restrict__ p0,
                            const float* __restrict__ cnt,
                            const float* __restrict__ Wf,  const float* __restrict__ bf,
                            const float* __restrict__ Wc1, const float* __restrict__ bc1,
                            const float* __restrict__ Wc2, const float* __restrict__ bc2,
                            float* __restrict__ out)
{
    __shared__ float xc[512];
    __shared__ float f[256];
    __shared__ float c1[128];
    __shared__ float lg[20];

    int b = blockIdx.x, t = threadIdx.x;
    float c = fmaxf(cnt[b], 1.f);
    xc[t]       = p2[b * 256 + t] / c;
    xc[256 + t] = p0[b * 256 + t] / c;
    __syncthreads();

    float acc = bf[t];
    for (int i = 0; i < 512; i++) acc += xc[i] * Wf[i * 256 + t];
    f[t] = fmaxf(acc, 0.f);
    __syncthreads();

    if (t < 128) {
        float a = bc1[t];
        for (int i = 0; i < 256; i++) a += f[i] * Wc1[i * 128 + t];
        c1[t] = fmaxf(a, 0.f);
    }
    __syncthreads();

    if (t < 20) {
        float a = bc2[t];
        for (int i = 0; i < 128; i++) a += c1[i] * Wc2[i * 20 + t];
        lg[t] = a;
    }
    __syncthreads();

    if (t < 32) {
        float v = (t < 20) ? lg[t] : -1e30f;
        float m = v;
#pragma unroll
        for (int o = 1; o < 32; o <<= 1) m = fmaxf(m, __shfl_xor_sync(0xffffffffu, m, o));
        float e = (t < 20) ? expf(v - m) : 0.f;
        float s = e;
#pragma unroll
        for (int o = 1; o < 32; o <<= 1) s += __shfl_xor_sync(0xffffffffu, s, o);
        if (t < 20) out[b * 20 + t] = v - m - logf(s);
    }
}

// ---------------- launcher -------------------------------------------------
extern "C" void kernel_launch(void* const* d_in, const int* in_sizes, int n_in,
                              void* d_out, int out_size)
{
    const float* x    = (const float*)d_in[0];
    const int*   ei   = (const int*)  d_in[1];
    const int*   batch= (const int*)  d_in[2];
    const float* W_in = (const float*)d_in[3];
    const float* b_in = (const float*)d_in[4];
    const float* W1   = (const float*)d_in[5];
    const float* as1  = (const float*)d_in[6];
    const float* ad1  = (const float*)d_in[7];
    const float* b1   = (const float*)d_in[8];
    const float* g1   = (const float*)d_in[9];
    const float* be1  = (const float*)d_in[10];
    const float* W2   = (const float*)d_in[11];
    const float* as2  = (const float*)d_in[12];
    const float* ad2  = (const float*)d_in[13];
    const float* b2   = (const float*)d_in[14];
    const float* g2   = (const float*)d_in[15];
    const float* be2  = (const float*)d_in[16];
    const float* Wf   = (const float*)d_in[17];
    const float* bfv  = (const float*)d_in[18];
    const float* Wc1  = (const float*)d_in[19];
    const float* bc1  = (const float*)d_in[20];
    const float* Wc2  = (const float*)d_in[21];
    const float* bc2  = (const float*)d_in[22];
    float* out = (float*)d_out;

    float *x0, *x1, *h, *ssrc, *sdst, *p2, *p0, *cnt;
    int *deg, *off, *pos, *csr, *bsum;
    __nv_bfloat16 *wbh, *wbl, *w1h, *w1l, *w2h, *w2l;
    cudaGetSymbolAddress((void**)&x0,  g_x0);
    cudaGetSymbolAddress((void**)&x1,  g_x1);
    cudaGetSymbolAddress((void**)&h,   g_h);
    cudaGetSymbolAddress((void**)&ssrc,g_ssrc);
    cudaGetSymbolAddress((void**)&sdst,g_sdst);
    cudaGetSymbolAddress((void**)&deg, g_deg);
    cudaGetSymbolAddress((void**)&off, g_off);
    cudaGetSymbolAddress((void**)&pos, g_pos);
    cudaGetSymbolAddress((void**)&csr, g_csr);
    cudaGetSymbolAddress((void**)&bsum,g_bsum);
    cudaGetSymbolAddress((void**)&p2,  g_p2);
    cudaGetSymbolAddress((void**)&p0,  g_p0);
    cudaGetSymbolAddress((void**)&cnt, g_cnt);
    cudaGetSymbolAddress((void**)&wbh, g_wbt_hi);
    cudaGetSymbolAddress((void**)&wbl, g_wbt_lo);
    cudaGetSymbolAddress((void**)&w1h, g_w1t_hi);
    cudaGetSymbolAddress((void**)&w1l, g_w1t_lo);
    cudaGetSymbolAddress((void**)&w2h, g_w2t_hi);
    cudaGetSymbolAddress((void**)&w2l, g_w2t_lo);

    cudaFuncSetAttribute(mm_mma_kernel, cudaFuncAttributeMaxDynamicSharedMemorySize, MM_SMEM);

    const int WARP_BLOCKS = NN / 8;
    const dim3 MMGRID((NN + 127) / 128, 2);   // 313 x 2

    // 0: big weight prep (coalesced transpose)
    wprep_kernel<<<dim3(KPBIG / 32, 8), 256>>>(W_in, wbh, wbl, KBIG, KPBIG);
    // 1-2: degree
    deg_init_kernel<<<(NN + 255) / 256, 256>>>(deg);
    deg_count_kernel<<<(EE + 255) / 256, 256>>>(ei, deg);
    // 3: BIG GEMM  <- ncu captures launch index 3
    mm_mma_kernel<<<MMGRID, 256, MM_SMEM>>>(x, wbh, wbl, b_in, x0, NN, KBIG, KPBIG);
    // 4-6: scan (coalesced, multi-block)
    scan_sum_kernel<<<SCB, 256>>>(deg, bsum);
    scan_top_kernel<<<1, 256>>>(bsum, off);
    scan_final_kernel<<<SCB, 256>>>(deg, bsum, off, pos);
    // 7: csr fill
    csr_fill_kernel<<<(ETOT + 255) / 256, 256>>>(ei, pos, csr);
    // conv weight preps
    wprep_kernel<<<dim3(256 / 32, 8), 256>>>(W1, w1h, w1l, 256, 256);
    wprep_kernel<<<dim3(256 / 32, 8), 256>>>(W2, w2h, w2l, 256, 256);

    // conv1
    mm_mma_kernel<<<MMGRID, 256, MM_SMEM>>>(x0, w1h, w1l, nullptr, h, NN, 256, 256);
    scores_kernel<8, 32><<<WARP_BLOCKS, 256>>>(h, as1, ad1, ssrc, sdst);
    agg_fused_kernel<8, 32, false><<<WARP_BLOCKS, 256>>>(
        ssrc, sdst, h, off, csr, b1, x0, g1, be1, x1,
        nullptr, nullptr, nullptr, nullptr, nullptr);

    // conv2 (+ fused pooling)
    mm_mma_kernel<<<MMGRID, 256, MM_SMEM>>>(x1, w2h, w2l, nullptr, h, NN, 256, 256);
    scores_kernel<4, 64><<<WARP_BLOCKS, 256>>>(h, as2, ad2, ssrc, sdst);
    pool_init_kernel<<<64, 256>>>(p2, p0, cnt);
    agg_fused_kernel<4, 64, true><<<WARP_BLOCKS, 256>>>(
        ssrc, sdst, h, off, csr, b2, x1, g2, be2, nullptr,
        x0, batch, p2, p0, cnt);

    // head
    head_kernel<<<BB, 256>>>(p2, p0, cnt, Wf, bfv, Wc1, bc1, Wc2, bc2, out);
}

// round 11
// speedup vs baseline: 1.7045x; 1.7045x over previous
#include <cuda_runtime.h>
#include <cuda_bf16.h>
#include <math.h>
#include <cstdint>

#define NN 40000
#define EE 1280000
#define ETOT (EE + NN)
#define DD 256
#define BB 64
#define NCLS 20
#define KBIG 5000
#define KPBIG 5024   /* 157 * 32 */
#define SCB 157      /* ceil(NN/256) scan blocks */

// ---------------- scratch (static device allocations) ----------------------
__device__ float g_x0[NN * DD];
__device__ float g_x1[NN * DD];
__device__ float g_h[NN * DD];
__device__ float g_ssrc[NN * 8];
__device__ float g_sdst[NN * 8];
__device__ int   g_deg[NN];
__device__ int   g_off[NN + 1];
__device__ int   g_pos[NN];
__device__ int   g_csr[ETOT];
__device__ int   g_bsum[256];
__device__ float g_p2[BB * DD];
__device__ float g_p0[BB * DD];
__device__ float g_cnt[BB];
__device__ __nv_bfloat16 g_wbt_hi[256 * KPBIG];
__device__ __nv_bfloat16 g_wbt_lo[256 * KPBIG];
__device__ __nv_bfloat16 g_w1t_hi[256 * 256];
__device__ __nv_bfloat16 g_w1t_lo[256 * 256];
__device__ __nv_bfloat16 g_w2t_hi[256 * 256];
__device__ __nv_bfloat16 g_w2t_lo[256 * 256];

__device__ __forceinline__ uint32_t bf2pack(float a, float b) {
    __nv_bfloat162 t;
    t.x = __float2bfloat16(a);
    t.y = __float2bfloat16(b);
    return *reinterpret_cast<uint32_t*>(&t);
}

__device__ __forceinline__ void mma16816(float* c, const uint32_t* a, const uint32_t* b) {
    asm volatile(
        "mma.sync.aligned.m16n8k16.row.col.f32.bf16.bf16.f32 "
        "{%0,%1,%2,%3}, {%4,%5,%6,%7}, {%8,%9}, {%0,%1,%2,%3};"
        : "+f"(c[0]), "+f"(c[1]), "+f"(c[2]), "+f"(c[3])
        : "r"(a[0]), "r"(a[1]), "r"(a[2]), "r"(a[3]), "r"(b[0]), "r"(b[1]));
}

// ------- weight prep (coalesced transpose): W[K,256] -> Wt[256,KP] hi/lo ----
__global__ void wprep_kernel(const float* __restrict__ W,
                             __nv_bfloat16* __restrict__ th,
                             __nv_bfloat16* __restrict__ tl, int K, int KP)
{
    __shared__ float tile[32][33];
    const int kb = blockIdx.x * 32, nb = blockIdx.y * 32;
    const int tx = threadIdx.x & 31, ty = threadIdx.x >> 5;
#pragma unroll
    for (int r = ty; r < 32; r += 8) {
        int k = kb + r;
        tile[r][tx] = (k < K) ? __ldg(&W[(size_t)k * 256 + nb + tx]) : 0.f;
    }
    __syncthreads();
#pragma unroll
    for (int r = ty; r < 32; r += 8) {
        int n = nb + r, k = kb + tx;
        float v = tile[tx][r];
        __nv_bfloat16 h = __float2bfloat16(v);
        th[(size_t)n * KP + k] = h;
        tl[(size_t)n * KP + k] = __float2bfloat16(v - __bfloat162float(h));
    }
}

// ---------------- mma.sync GEMM: 512 threads, 16 warps, warp tile 32x32 -----
#define KROWB 80
#define ABUF_H 0
#define ABUF_L (128 * KROWB)
#define BBUF_H (2 * 128 * KROWB)
#define BBUF_L (3 * 128 * KROWB)
#define BUFSZ  (4 * 128 * KROWB)
#define MM_SMEM (2 * BUFSZ)

__global__ void __launch_bounds__(512, 1)
mm_mma_kernel(const float* __restrict__ A,
              const __nv_bfloat16* __restrict__ Bh,
              const __nv_bfloat16* __restrict__ Bl,
              const float* __restrict__ bias,
              float* __restrict__ C, int M, int Kdim, int KP)
{
    extern __shared__ char smem[];
    const int tid = threadIdx.x, wid = tid >> 5, lane = tid & 31;
    const int group = lane >> 2, tig = lane & 3;
    const int rg = wid >> 2, cg = wid & 3;          // 4 row-groups x 4 col-groups
    const int r0 = blockIdx.x * 128, n0 = blockIdx.y * 128;

    float acc[2][4][4];
#pragma unroll
    for (int mt = 0; mt < 2; mt++)
#pragma unroll
        for (int nt = 0; nt < 4; nt++)
#pragma unroll
            for (int j = 0; j < 4; j++) acc[mt][nt][j] = 0.f;

    const int NCH = KP >> 5;
    const int arow = tid >> 2;              // 0..127
    const int acol0 = (tid & 3) * 8;        // 0,8,16,24
    const bool arok = (r0 + arow) < M;
    const float* Abase = A + (size_t)(r0 + arow) * Kdim;
    const int bn = tid >> 2, bseg = tid & 3;

    float apf[8];
    uint4 bpfh, bpfl;

#define LDG_CHUNK(K0) do {                                                   \
    _Pragma("unroll")                                                        \
    for (int ii = 0; ii < 2; ii++) {                                         \
        int c = (K0) + acol0 + ii * 4;                                       \
        float4 v = make_float4(0.f, 0.f, 0.f, 0.f);                          \
        if (arok) {                                                          \
            if (c + 3 < Kdim) v = *(const float4*)(Abase + c);               \
            else {                                                           \
                if (c     < Kdim) v.x = Abase[c];                            \
                if (c + 1 < Kdim) v.y = Abase[c + 1];                        \
                if (c + 2 < Kdim) v.z = Abase[c + 2];                        \
                if (c + 3 < Kdim) v.w = Abase[c + 3];                        \
            }                                                                \
        }                                                                    \
        apf[ii*4+0] = v.x; apf[ii*4+1] = v.y;                                \
        apf[ii*4+2] = v.z; apf[ii*4+3] = v.w;                                \
    }                                                                        \
    {                                                                        \
        size_t so = (size_t)(n0 + bn) * KP + (K0) + bseg * 8;                \
        bpfh = *(const uint4*)(Bh + so);                                     \
        bpfl = *(const uint4*)(Bl + so);                                     \
    }                                                                        \
} while (0)

    LDG_CHUNK(0);

    for (int i = 0; i < NCH; i++) {
        char* buf = smem + (size_t)(i & 1) * BUFSZ;

        // ---- STS (convert A fp32 -> bf16 hi/lo; B passthrough) ----
        {
            uint32_t ph[4], pl[4];
#pragma unroll
            for (int j = 0; j < 4; j++) {
                float vx = apf[2 * j], vy = apf[2 * j + 1];
                float hx = __bfloat162float(__float2bfloat16(vx));
                float hy = __bfloat162float(__float2bfloat16(vy));
                ph[j] = bf2pack(vx, vy);
                pl[j] = bf2pack(vx - hx, vy - hy);
            }
            uint32_t aoff = arow * KROWB + acol0 * 2;
            *(uint4*)(buf + ABUF_H + aoff) = make_uint4(ph[0], ph[1], ph[2], ph[3]);
            *(uint4*)(buf + ABUF_L + aoff) = make_uint4(pl[0], pl[1], pl[2], pl[3]);
            uint32_t boff = bn * KROWB + bseg * 16;
            *(uint4*)(buf + BBUF_H + boff) = bpfh;
            *(uint4*)(buf + BBUF_L + boff) = bpfl;
        }
        __syncthreads();

        if (i + 1 < NCH) LDG_CHUNK((i + 1) << 5);

        // ---- compute: 2 k-steps x (hh, hl, lh) ----
#pragma unroll
        for (int ks = 0; ks < 2; ks++) {
            const uint32_t kb = (uint32_t)(ks * 16 + tig * 2) * 2;
            uint32_t ah[2][4], bhf[4][2], blf[4][2], alf[2][4];
#pragma unroll
            for (int mt = 0; mt < 2; mt++) {
                uint32_t rb = (uint32_t)(rg * 32 + mt * 16 + group) * KROWB;
                ah[mt][0] = *(const uint32_t*)(buf + ABUF_H + rb + kb);
                ah[mt][1] = *(const uint32_t*)(buf + ABUF_H + rb + 8 * KROWB + kb);
                ah[mt][2] = *(const uint32_t*)(buf + ABUF_H + rb + kb + 16);
                ah[mt][3] = *(const uint32_t*)(buf + ABUF_H + rb + 8 * KROWB + kb + 16);
            }
#pragma unroll
            for (int nt = 0; nt < 4; nt++) {
                uint32_t nb = (uint32_t)(cg * 32 + nt * 8 + group) * KROWB;
                bhf[nt][0] = *(const uint32_t*)(buf + BBUF_H + nb + kb);
                bhf[nt][1] = *(const uint32_t*)(buf + BBUF_H + nb + kb + 16);
            }
#pragma unroll
            for (int mt = 0; mt < 2; mt++)
#pragma unroll
                for (int nt = 0; nt < 4; nt++)
                    mma16816(acc[mt][nt], ah[mt], bhf[nt]);
#pragma unroll
            for (int nt = 0; nt < 4; nt++) {
                uint32_t nb = (uint32_t)(cg * 32 + nt * 8 + group) * KROWB;
                blf[nt][0] = *(const uint32_t*)(buf + BBUF_L + nb + kb);
                blf[nt][1] = *(const uint32_t*)(buf + BBUF_L + nb + kb + 16);
            }
#pragma unroll
            for (int mt = 0; mt < 2; mt++)
#pragma unroll
                for (int nt = 0; nt < 4; nt++)
                    mma16816(acc[mt][nt], ah[mt], blf[nt]);
#pragma unroll
            for (int mt = 0; mt < 2; mt++) {
                uint32_t rb = (uint32_t)(rg * 32 + mt * 16 + group) * KROWB;
                alf[mt][0] = *(const uint32_t*)(buf + ABUF_L + rb + kb);
                alf[mt][1] = *(const uint32_t*)(buf + ABUF_L + rb + 8 * KROWB + kb);
                alf[mt][2] = *(const uint32_t*)(buf + ABUF_L + rb + kb + 16);
                alf[mt][3] = *(const uint32_t*)(buf + ABUF_L + rb + 8 * KROWB + kb + 16);
            }
#pragma unroll
            for (int mt = 0; mt < 2; mt++)
#pragma unroll
                for (int nt = 0; nt < 4; nt++)
                    mma16816(acc[mt][nt], alf[mt], bhf[nt]);
        }
    }

    // ---- epilogue ----
#pragma unroll
    for (int nt = 0; nt < 4; nt++) {
        int c = n0 + cg * 32 + nt * 8 + tig * 2;
        float b0v = bias ? __ldg(bias + c) : 0.f;
        float b1v = bias ? __ldg(bias + c + 1) : 0.f;
#pragma unroll
        for (int mt = 0; mt < 2; mt++) {
            int r = r0 + rg * 32 + mt * 16 + group;
            if (r < M)
                *(float2*)(C + (size_t)r * 256 + c) =
                    make_float2(acc[mt][nt][0] + b0v, acc[mt][nt][1] + b1v);
            if (r + 8 < M)
                *(float2*)(C + (size_t)(r + 8) * 256 + c) =
                    make_float2(acc[mt][nt][2] + b0v, acc[mt][nt][3] + b1v);
        }
    }
#undef LDG_CHUNK
}

// ---------------- CSR build ------------------------------------------------
__global__ void deg_init_kernel(int* deg) {
    int i = blockIdx.x * blockDim.x + threadIdx.x;
    if (i < NN) deg[i] = 1;
}
__global__ void deg_count_kernel(const int* __restrict__ ei, int* deg) {
    int i = blockIdx.x * blockDim.x + threadIdx.x;
    if (i < EE) atomicAdd(&deg[ei[EE + i]], 1);
}

// --- 3-kernel coalesced scan ---
__global__ void scan_sum_kernel(const int* __restrict__ deg, int* __restrict__ bsum) {
    int i = blockIdx.x * 256 + threadIdx.x;
    int lane = threadIdx.x & 31, wid = threadIdx.x >> 5;
    int d = (i < NN) ? deg[i] : 0;
#pragma unroll
    for (int o = 16; o > 0; o >>= 1) d += __shfl_xor_sync(0xffffffffu, d, o);
    __shared__ int ws[8];
    if (lane == 0) ws[wid] = d;
    __syncthreads();
    if (threadIdx.x == 0) {
        int s = 0;
#pragma unroll
        for (int w = 0; w < 8; w++) s += ws[w];
        bsum[blockIdx.x] = s;
    }
}
__global__ void scan_top_kernel(int* __restrict__ bsum, int* __restrict__ off) {
    int t = threadIdx.x, lane = t & 31, wid = t >> 5;
    int v = (t < SCB) ? bsum[t] : 0;
    int x = v;
#pragma unroll
    for (int o = 1; o < 32; o <<= 1) {
        int y = __shfl_up_sync(0xffffffffu, x, o);
        if (lane >= o) x += y;
    }
    __shared__ int ws[8];
    if (lane == 31) ws[wid] = x;
    __syncthreads();
    int wpre = 0;
#pragma unroll
    for (int w = 0; w < 8; w++) if (w < wid) wpre += ws[w];
    int incl = x + wpre;
    if (t < SCB) bsum[t] = incl - v;
    if (t == 255) off[NN] = incl;
}
__global__ void scan_final_kernel(const int* __restrict__ deg,
                                  const int* __restrict__ bsum,
                                  int* __restrict__ off, int* __restrict__ pos) {
    int i = blockIdx.x * 256 + threadIdx.x;
    int lane = threadIdx.x & 31, wid = threadIdx.x >> 5;
    int d = (i < NN) ? deg[i] : 0;
    int x = d;
#pragma unroll
    for (int o = 1; o < 32; o <<= 1) {
        int y = __shfl_up_sync(0xffffffffu, x, o);
        if (lane >= o) x += y;
    }
    __shared__ int ws[8];
    if (lane == 31) ws[wid] = x;
    __syncthreads();
    int wpre = 0;
#pragma unroll
    for (int w = 0; w < 8; w++) if (w < wid) wpre += ws[w];
    int excl = x - d + wpre + bsum[blockIdx.x];
    if (i < NN) { off[i] = excl; pos[i] = excl; }
}

__global__ void csr_fill_kernel(const int* __restrict__ ei, int* pos, int* csr) {
    int i = blockIdx.x * blockDim.x + threadIdx.x;
    if (i >= ETOT) return;
    int s, d;
    if (i < EE) { s = ei[i]; d = ei[EE + i]; }
    else        { s = d = i - EE; }
    int p = atomicAdd(&pos[d], 1);
    csr[p] = s;
}

// ---------------- attention scores ----------------------------------------
template <int H, int C>
__global__ void scores_kernel(const float* __restrict__ h,
                              const float* __restrict__ asrc,
                              const float* __restrict__ adst,
                              float* __restrict__ ssrc, float* __restrict__ sdst)
{
    int gw = (blockIdx.x * blockDim.x + threadIdx.x) >> 5;
    if (gw >= NN) return;
    int lane = threadIdx.x & 31;

    const float4* hp = (const float4*)(h + gw * 256 + lane * 8);
    float4 v0 = hp[0], v1 = hp[1];
    const float4* ap = (const float4*)(asrc + lane * 8);
    float4 a0 = ap[0], a1 = ap[1];
    const float4* dp = (const float4*)(adst + lane * 8);
    float4 d0 = dp[0], d1 = dp[1];

    float ps = v0.x * a0.x + v0.y * a0.y + v0.z * a0.z + v0.w * a0.w +
               v1.x * a1.x + v1.y * a1.y + v1.z * a1.z + v1.w * a1.w;
    float pd = v0.x * d0.x + v0.y * d0.y + v0.z * d0.z + v0.w * d0.w +
               v1.x * d1.x + v1.y * d1.y + v1.z * d1.z + v1.w * d1.w;

    const int GC = C / 8;
#pragma unroll
    for (int o = 1; o < GC; o <<= 1) {
        ps += __shfl_xor_sync(0xffffffffu, ps, o);
        pd += __shfl_xor_sync(0xffffffffu, pd, o);
    }
    int myh = lane / GC;
    if ((lane & (GC - 1)) == 0) {
        ssrc[gw * H + myh] = ps;
        sdst[gw * H + myh] = pd;
    }
}

// ------- GAT aggregation fused with bias+elu+residual+LN (+ pooling) -------
template <int H, int C, bool POOL>
__global__ void agg_fused_kernel(const float* __restrict__ ssrc,
                                 const float* __restrict__ sdst,
                                 const float* __restrict__ h,
                                 const int* __restrict__ off,
                                 const int* __restrict__ csr,
                                 const float* __restrict__ bias,
                                 const float* __restrict__ xin,
                                 const float* __restrict__ g,
                                 const float* __restrict__ be,
                                 float* __restrict__ xout,
                                 const float* __restrict__ x0p,
                                 const int* __restrict__ batch,
                                 float* __restrict__ p2,
                                 float* __restrict__ p0,
                                 float* __restrict__ cnt)
{
    int gw = (blockIdx.x * blockDim.x + threadIdx.x) >> 5;
    if (gw >= NN) return;
    int lane = threadIdx.x & 31;

    int e0 = off[gw];
    int deg = off[gw + 1] - e0;

    const int ES = 32 / H;
    int hh = lane % H;
    int j0 = lane / H;

    float sd = __ldg(&sdst[gw * H + hh]);
    float m = -1e30f, z = 0.f;
    for (int j = j0; j < deg; j += ES) {
        int s = __ldg(&csr[e0 + j]);
        float e = __ldg(&ssrc[s * H + hh]) + sd;
        e = e > 0.f ? e : 0.2f * e;
        float mn = fmaxf(m, e);
        z = z * __expf(m - mn) + __expf(e - mn);
        m = mn;
    }
#pragma unroll
    for (int o = H; o < 32; o <<= 1) {
        float mo = __shfl_xor_sync(0xffffffffu, m, o);
        float zo = __shfl_xor_sync(0xffffffffu, z, o);
        float mn = fmaxf(m, mo);
        z = z * __expf(m - mn) + zo * __expf(mo - mn);
        m = mn;
    }

    const int myh = (lane * 8) / C;
    float my_m  = __shfl_sync(0xffffffffu, m, myh);
    float my_zi = 1.f / __shfl_sync(0xffffffffu, z, myh);
    float my_sd = __ldg(&sdst[gw * H + myh]);

    float acc[8] = {0.f, 0.f, 0.f, 0.f, 0.f, 0.f, 0.f, 0.f};
    for (int j = 0; j < deg; j++) {
        int s = __ldg(&csr[e0 + j]);
        float e = __ldg(&ssrc[s * H + myh]) + my_sd;
        e = e > 0.f ? e : 0.2f * e;
        float a = __expf(e - my_m) * my_zi;
        const float4* hp = (const float4*)(h + s * 256 + lane * 8);
        float4 v0 = __ldg(hp);
        float4 v1 = __ldg(hp + 1);
        acc[0] += a * v0.x; acc[1] += a * v0.y; acc[2] += a * v0.z; acc[3] += a * v0.w;
        acc[4] += a * v1.x; acc[5] += a * v1.y; acc[6] += a * v1.z; acc[7] += a * v1.w;
    }

    int base = gw * 256 + lane * 8;
    float4 b0 = *(const float4*)(bias + lane * 8);
    float4 b1 = *(const float4*)(bias + lane * 8 + 4);
    float4 x0v = *(const float4*)(xin + base);
    float4 x1v = *(const float4*)(xin + base + 4);
    float bb[8] = {b0.x, b0.y, b0.z, b0.w, b1.x, b1.y, b1.z, b1.w};
    float xv[8] = {x0v.x, x0v.y, x0v.z, x0v.w, x1v.x, x1v.y, x1v.z, x1v.w};

    float v[8];
    float sum = 0.f, sq = 0.f;
#pragma unroll
    for (int k = 0; k < 8; k++) {
        float t = acc[k] + bb[k];
        t = (t > 0.f) ? t : (__expf(t) - 1.f);
        t += xv[k];
        v[k] = t;
        sum += t;
        sq += t * t;
    }
#pragma unroll
    for (int o = 1; o < 32; o <<= 1) {
        sum += __shfl_xor_sync(0xffffffffu, sum, o);
        sq  += __shfl_xor_sync(0xffffffffu, sq, o);
    }
    float mean = sum * (1.f / 256.f);
    float var  = sq * (1.f / 256.f) - mean * mean;
    float rs   = rsqrtf(var + 1e-5f);

    float4 g0 = *(const float4*)(g + lane * 8);
    float4 g1 = *(const float4*)(g + lane * 8 + 4);
    float4 e0v = *(const float4*)(be + lane * 8);
    float4 e1v = *(const float4*)(be + lane * 8 + 4);
    float gv[8] = {g0.x, g0.y, g0.z, g0.w, g1.x, g1.y, g1.z, g1.w};
    float ev[8] = {e0v.x, e0v.y, e0v.z, e0v.w, e1v.x, e1v.y, e1v.z, e1v.w};

    float o0[8];
#pragma unroll
    for (int k = 0; k < 8; k++) o0[k] = (v[k] - mean) * rs * gv[k] + ev[k];

    if (!POOL) {
        *(float4*)(xout + base)     = make_float4(o0[0], o0[1], o0[2], o0[3]);
        *(float4*)(xout + base + 4) = make_float4(o0[4], o0[5], o0[6], o0[7]);
    } else {
        int b = __ldg(&batch[gw]);
        float* pp2 = p2 + b * 256 + lane * 8;
        float* pp0 = p0 + b * 256 + lane * 8;
        float4 z0 = *(const float4*)(x0p + base);
        float4 z1 = *(const float4*)(x0p + base + 4);
        float zv[8] = {z0.x, z0.y, z0.z, z0.w, z1.x, z1.y, z1.z, z1.w};
#pragma unroll
        for (int k = 0; k < 8; k++) {
            atomicAdd(pp2 + k, o0[k]);
            atomicAdd(pp0 + k, zv[k]);
        }
        if (lane == 0) atomicAdd(&cnt[b], 1.f);
    }
}

// ---------------- pooling init ---------------------------------------------
__global__ void pool_init_kernel(float* p2, float* p0, float* cnt) {
    int i = blockIdx.x * blockDim.x + threadIdx.x;
    if (i < BB * DD) { p2[i] = 0.f; p0[i] = 0.f; }
    if (i < BB) cnt[i] = 0.f;
}

// ---------------- classification head (block per graph) -------------------
__global__ void head_kernel(const float* __restrict__ p2,
                            const float* __restrict__ p0,
                            const float* __restrict__ cnt,
                            const float* __restrict__ Wf,  const float* __restrict__ bf,
                            const float* __restrict__ Wc1, const float* __restrict__ bc1,
                            const float* __restrict__ Wc2, const float* __restrict__ bc2,
                            float* __restrict__ out)
{
    __shared__ float xc[512];
    __shared__ float f[256];
    __shared__ float c1[128];
    __shared__ float lg[20];

    int b = blockIdx.x, t = threadIdx.x;
    float c = fmaxf(cnt[b], 1.f);
    xc[t]       = p2[b * 256 + t] / c;
    xc[256 + t] = p0[b * 256 + t] / c;
    __syncthreads();

    float acc = bf[t];
    for (int i = 0; i < 512; i++) acc += xc[i] * Wf[i * 256 + t];
    f[t] = fmaxf(acc, 0.f);
    __syncthreads();

    if (t < 128) {
        float a = bc1[t];
        for (int i = 0; i < 256; i++) a += f[i] * Wc1[i * 128 + t];
        c1[t] = fmaxf(a, 0.f);
    }
    __syncthreads();

    if (t < 20) {
        float a = bc2[t];
        for (int i = 0; i < 128; i++) a += c1[i] * Wc2[i * 20 + t];
        lg[t] = a;
    }
    __syncthreads();

    if (t < 32) {
        float v = (t < 20) ? lg[t] : -1e30f;
        float m = v;
#pragma unroll
        for (int o = 1; o < 32; o <<= 1) m = fmaxf(m, __shfl_xor_sync(0xffffffffu, m, o));
        float e = (t < 20) ? expf(v - m) : 0.f;
        float s = e;
#pragma unroll
        for (int o = 1; o < 32; o <<= 1) s += __shfl_xor_sync(0xffffffffu, s, o);
        if (t < 20) out[b * 20 + t] = v - m - logf(s);
    }
}

// ---------------- launcher -------------------------------------------------
extern "C" void kernel_launch(void* const* d_in, const int* in_sizes, int n_in,
                              void* d_out, int out_size)
{
    const float* x    = (const float*)d_in[0];
    const int*   ei   = (const int*)  d_in[1];
    const int*   batch= (const int*)  d_in[2];
    const float* W_in = (const float*)d_in[3];
    const float* b_in = (const float*)d_in[4];
    const float* W1   = (const float*)d_in[5];
    const float* as1  = (const float*)d_in[6];
    const float* ad1  = (const float*)d_in[7];
    const float* b1   = (const float*)d_in[8];
    const float* g1   = (const float*)d_in[9];
    const float* be1  = (const float*)d_in[10];
    const float* W2   = (const float*)d_in[11];
    const float* as2  = (const float*)d_in[12];
    const float* ad2  = (const float*)d_in[13];
    const float* b2   = (const float*)d_in[14];
    const float* g2   = (const float*)d_in[15];
    const float* be2  = (const float*)d_in[16];
    const float* Wf   = (const float*)d_in[17];
    const float* bfv  = (const float*)d_in[18];
    const float* Wc1  = (const float*)d_in[19];
    const float* bc1  = (const float*)d_in[20];
    const float* Wc2  = (const float*)d_in[21];
    const float* bc2  = (const float*)d_in[22];
    float* out = (float*)d_out;

    float *x0, *x1, *h, *ssrc, *sdst, *p2, *p0, *cnt;
    int *deg, *off, *pos, *csr, *bsum;
    __nv_bfloat16 *wbh, *wbl, *w1h, *w1l, *w2h, *w2l;
    cudaGetSymbolAddress((void**)&x0,  g_x0);
    cudaGetSymbolAddress((void**)&x1,  g_x1);
    cudaGetSymbolAddress((void**)&h,   g_h);
    cudaGetSymbolAddress((void**)&ssrc,g_ssrc);
    cudaGetSymbolAddress((void**)&sdst,g_sdst);
    cudaGetSymbolAddress((void**)&deg, g_deg);
    cudaGetSymbolAddress((void**)&off, g_off);
    cudaGetSymbolAddress((void**)&pos, g_pos);
    cudaGetSymbolAddress((void**)&csr, g_csr);
    cudaGetSymbolAddress((void**)&bsum,g_bsum);
    cudaGetSymbolAddress((void**)&p2,  g_p2);
    cudaGetSymbolAddress((void**)&p0,  g_p0);
    cudaGetSymbolAddress((void**)&cnt, g_cnt);
    cudaGetSymbolAddress((void**)&wbh, g_wbt_hi);
    cudaGetSymbolAddress((void**)&wbl, g_wbt_lo);
    cudaGetSymbolAddress((void**)&w1h, g_w1t_hi);
    cudaGetSymbolAddress((void**)&w1l, g_w1t_lo);
    cudaGetSymbolAddress((void**)&w2h, g_w2t_hi);
    cudaGetSymbolAddress((void**)&w2l, g_w2t_lo);

    cudaFuncSetAttribute(mm_mma_kernel, cudaFuncAttributeMaxDynamicSharedMemorySize, MM_SMEM);

    const int WARP_BLOCKS = NN / 8;
    const dim3 MMGRID((NN + 127) / 128, 2);   // 313 x 2

    // 0: big weight prep (coalesced transpose)
    wprep_kernel<<<dim3(KPBIG / 32, 8), 256>>>(W_in, wbh, wbl, KBIG, KPBIG);
    // 1-2: degree
    deg_init_kernel<<<(NN + 255) / 256, 256>>>(deg);
    deg_count_kernel<<<(EE + 255) / 256, 256>>>(ei, deg);
    // 3: BIG GEMM  <- ncu captures launch index 3
    mm_mma_kernel<<<MMGRID, 512, MM_SMEM>>>(x, wbh, wbl, b_in, x0, NN, KBIG, KPBIG);
    // 4-6: scan (coalesced, multi-block)
    scan_sum_kernel<<<SCB, 256>>>(deg, bsum);
    scan_top_kernel<<<1, 256>>>(bsum, off);
    scan_final_kernel<<<SCB, 256>>>(deg, bsum, off, pos);
    // 7: csr fill
    csr_fill_kernel<<<(ETOT + 255) / 256, 256>>>(ei, pos, csr);
    // conv weight preps
    wprep_kernel<<<dim3(256 / 32, 8), 256>>>(W1, w1h, w1l, 256, 256);
    wprep_kernel<<<dim3(256 / 32, 8), 256>>>(W2, w2h, w2l, 256, 256);

    // conv1
    mm_mma_kernel<<<MMGRID, 512, MM_SMEM>>>(x0, w1h, w1l, nullptr, h, NN, 256, 256);
    scores_kernel<8, 32><<<WARP_BLOCKS, 256>>>(h, as1, ad1, ssrc, sdst);
    agg_fused_kernel<8, 32, false><<<WARP_BLOCKS, 256>>>(
        ssrc, sdst, h, off, csr, b1, x0, g1, be1, x1,
        nullptr, nullptr, nullptr, nullptr, nullptr);

    // conv2 (+ fused pooling)
    mm_mma_kernel<<<MMGRID, 512, MM_SMEM>>>(x1, w2h, w2l, nullptr, h, NN, 256, 256);
    scores_kernel<4, 64><<<WARP_BLOCKS, 256>>>(h, as2, ad2, ssrc, sdst);
    pool_init_kernel<<<64, 256>>>(p2, p0, cnt);
    agg_fused_kernel<4, 64, true><<<WARP_BLOCKS, 256>>>(
        ssrc, sdst, h, off, csr, b2, x1, g2, be2, nullptr,
        x0, batch, p2, p0, cnt);

    // head
    head_kernel<<<BB, 256>>>(p2, p0, cnt, Wf, bfv, Wc1, bc1, Wc2, bc2, out);
}

// round 12
// speedup vs baseline: 1.7391x; 1.0203x over previous
#include <cuda_runtime.h>
#include <cuda_bf16.h>
#include <math.h>
#include <cstdint>

#define NN 40000
#define EE 1280000
#define ETOT (EE + NN)
#define DD 256
#define BB 64
#define NCLS 20
#define KBIG 5000
#define KPBIG 5056   /* 79 * 64 */
#define SCB 157      /* ceil(NN/256) scan blocks */

// ---------------- scratch (static device allocations) ----------------------
__device__ float g_x0[NN * DD];
__device__ float g_x1[NN * DD];
__device__ float g_h[NN * DD];
__device__ float g_ssrc[NN * 8];
__device__ float g_sdst[NN * 8];
__device__ int   g_deg[NN];
__device__ int   g_off[NN + 1];
__device__ int   g_pos[NN];
__device__ int   g_csr[ETOT];
__device__ int   g_bsum[256];
__device__ float g_p2[BB * DD];
__device__ float g_p0[BB * DD];
__device__ float g_cnt[BB];
__device__ __nv_bfloat16 g_wbt_hi[256 * KPBIG];
__device__ __nv_bfloat16 g_wbt_lo[256 * KPBIG];
__device__ __nv_bfloat16 g_w1t_hi[256 * 256];
__device__ __nv_bfloat16 g_w1t_lo[256 * 256];
__device__ __nv_bfloat16 g_w2t_hi[256 * 256];
__device__ __nv_bfloat16 g_w2t_lo[256 * 256];

__device__ __forceinline__ uint32_t smem_to_u32(const void* p) {
    uint32_t a;
    asm("{ .reg .u64 t; cvta.to.shared.u64 t, %1; cvt.u32.u64 %0, t; }"
        : "=r"(a) : "l"(p));
    return a;
}

__device__ __forceinline__ uint32_t bf2pack(float a, float b) {
    __nv_bfloat162 t;
    t.x = __float2bfloat16(a);
    t.y = __float2bfloat16(b);
    return *reinterpret_cast<uint32_t*>(&t);
}

__device__ __forceinline__ void mma16816(float* c, const uint32_t* a, const uint32_t* b) {
    asm volatile(
        "mma.sync.aligned.m16n8k16.row.col.f32.bf16.bf16.f32 "
        "{%0,%1,%2,%3}, {%4,%5,%6,%7}, {%8,%9}, {%0,%1,%2,%3};"
        : "+f"(c[0]), "+f"(c[1]), "+f"(c[2]), "+f"(c[3])
        : "r"(a[0]), "r"(a[1]), "r"(a[2]), "r"(a[3]), "r"(b[0]), "r"(b[1]));
}

__device__ __forceinline__ void ldsm4(uint32_t* r, uint32_t addr) {
    asm volatile("ldmatrix.sync.aligned.m8n8.x4.shared.b16 {%0,%1,%2,%3}, [%4];"
        : "=r"(r[0]), "=r"(r[1]), "=r"(r[2]), "=r"(r[3]) : "r"(addr));
}

// ------- weight prep (coalesced transpose): W[K,256] -> Wt[256,KP] hi/lo ----
__global__ void wprep_kernel(const float* __restrict__ W,
                             __nv_bfloat16* __restrict__ th,
                             __nv_bfloat16* __restrict__ tl, int K, int KP)
{
    __shared__ float tile[32][33];
    const int kb = blockIdx.x * 32, nb = blockIdx.y * 32;
    const int tx = threadIdx.x & 31, ty = threadIdx.x >> 5;
#pragma unroll
    for (int r = ty; r < 32; r += 8) {
        int k = kb + r;
        tile[r][tx] = (k < K) ? __ldg(&W[(size_t)k * 256 + nb + tx]) : 0.f;
    }
    __syncthreads();
#pragma unroll
    for (int r = ty; r < 32; r += 8) {
        int n = nb + r, k = kb + tx;
        float v = tile[tx][r];
        __nv_bfloat16 h = __float2bfloat16(v);
        th[(size_t)n * KP + k] = h;
        tl[(size_t)n * KP + k] = __float2bfloat16(v - __bfloat162float(h));
    }
}

// ---- mma.sync GEMM: 512 thr, 16 warps, warp tile 32x32, K-chunk 64, ldsm ---
#define KROWB 80
#define ABUF_H 0
#define ABUF_L 10240
#define BBUF_H 20480
#define BBUF_L 30720
#define SUBSZ  40960
#define BUFSZ  (2 * SUBSZ)      /* 81920: two 32-k sub-buffers */
#define MM_SMEM (2 * BUFSZ)     /* 163840 */

__global__ void __launch_bounds__(512, 1)
mm_mma_kernel(const float* __restrict__ A,
              const __nv_bfloat16* __restrict__ Bh,
              const __nv_bfloat16* __restrict__ Bl,
              const float* __restrict__ bias,
              float* __restrict__ C, int M, int Kdim, int KP)
{
    extern __shared__ char smem[];
    const uint32_t sb = smem_to_u32(smem);
    const int tid = threadIdx.x, wid = tid >> 5, lane = tid & 31;
    const int group = lane >> 2, tig = lane & 3;
    const int rg = wid >> 2, cg = wid & 3;          // 4 row-groups x 4 col-groups
    const int r0 = blockIdx.x * 128, n0 = blockIdx.y * 128;

    float acc[2][4][4];
#pragma unroll
    for (int mt = 0; mt < 2; mt++)
#pragma unroll
        for (int nt = 0; nt < 4; nt++)
#pragma unroll
            for (int j = 0; j < 4; j++) acc[mt][nt][j] = 0.f;

    const int NCH = KP >> 6;                 // 64-k chunks
    const int arow = tid >> 2;               // 0..127
    const int acol0 = (tid & 3) * 16;        // 0,16,32,48 (fp32 elements)
    const bool arok = (r0 + arow) < M;
    const float* Abase = A + (size_t)(r0 + arow) * Kdim;
    const int bn = tid >> 2, bseg = tid & 3; // B: 16 halves each

    float apf[16];
    uint4 bpfh[2], bpfl[2];

#define LDG_CHUNK(K0) do {                                                   \
    _Pragma("unroll")                                                        \
    for (int ii = 0; ii < 4; ii++) {                                         \
        int c = (K0) + acol0 + ii * 4;                                       \
        float4 v = make_float4(0.f, 0.f, 0.f, 0.f);                          \
        if (arok) {                                                          \
            if (c + 3 < Kdim) v = *(const float4*)(Abase + c);               \
            else {                                                           \
                if (c     < Kdim) v.x = Abase[c];                            \
                if (c + 1 < Kdim) v.y = Abase[c + 1];                        \
                if (c + 2 < Kdim) v.z = Abase[c + 2];                        \
                if (c + 3 < Kdim) v.w = Abase[c + 3];                        \
            }                                                                \
        }                                                                    \
        apf[ii*4+0] = v.x; apf[ii*4+1] = v.y;                                \
        apf[ii*4+2] = v.z; apf[ii*4+3] = v.w;                                \
    }                                                                        \
    {                                                                        \
        size_t so = (size_t)(n0 + bn) * KP + (K0) + bseg * 16;               \
        bpfh[0] = *(const uint4*)(Bh + so);                                  \
        bpfh[1] = *(const uint4*)(Bh + so + 8);                              \
        bpfl[0] = *(const uint4*)(Bl + so);                                  \
        bpfl[1] = *(const uint4*)(Bl + so + 8);                              \
    }                                                                        \
} while (0)

    LDG_CHUNK(0);

    // ldmatrix per-lane base offsets (proven mapping from R4)
    const uint32_t a_lm = (uint32_t)(rg * 32 + (lane & 15)) * KROWB + (lane >> 4) * 16;
    const int bmat = lane >> 3, brow = lane & 7;
    const uint32_t b_lm = (uint32_t)(cg * 32 + (bmat & 1) * 8 + brow) * KROWB + (bmat >> 1) * 16;

    for (int i = 0; i < NCH; i++) {
        char* buf = smem + (size_t)(i & 1) * BUFSZ;
        const uint32_t bufa = sb + (uint32_t)(i & 1) * BUFSZ;

        // ---- STS: A fp32 -> bf16 hi/lo, B passthrough; into 2 sub-buffers --
        {
            uint32_t ph[8], pl[8];
#pragma unroll
            for (int j = 0; j < 8; j++) {
                float vx = apf[2 * j], vy = apf[2 * j + 1];
                float hx = __bfloat162float(__float2bfloat16(vx));
                float hy = __bfloat162float(__float2bfloat16(vy));
                ph[j] = bf2pack(vx, vy);
                pl[j] = bf2pack(vx - hx, vy - hy);
            }
            // A: 16 elements -> one sub-buffer (acol0 16-aligned, 16 wide)
            int asub = acol0 >> 5;                 // 0 or 1
            int kloc = acol0 & 31;                 // 0 or 16
            char* ab = buf + asub * SUBSZ + arow * KROWB + kloc * 2;
            *(uint4*)(ab + ABUF_H)      = make_uint4(ph[0], ph[1], ph[2], ph[3]);
            *(uint4*)(ab + ABUF_H + 16) = make_uint4(ph[4], ph[5], ph[6], ph[7]);
            *(uint4*)(ab + ABUF_L)      = make_uint4(pl[0], pl[1], pl[2], pl[3]);
            *(uint4*)(ab + ABUF_L + 16) = make_uint4(pl[4], pl[5], pl[6], pl[7]);
            // B: 16 halves -> one sub-buffer
            int bsub = bseg >> 1;                  // 0 or 1
            int bkloc = (bseg & 1) * 16;           // halves
            char* bb = buf + bsub * SUBSZ + bn * KROWB + bkloc * 2;
            *(uint4*)(bb + BBUF_H)      = bpfh[0];
            *(uint4*)(bb + BBUF_H + 16) = bpfh[1];
            *(uint4*)(bb + BBUF_L)      = bpfl[0];
            *(uint4*)(bb + BBUF_L + 16) = bpfl[1];
        }
        __syncthreads();

        if (i + 1 < NCH) LDG_CHUNK((i + 1) << 6);

        // ---- compute: 2 sub-buffers x 2 k-steps x (hh, hl, lh) ----
#pragma unroll
        for (int sub = 0; sub < 2; sub++) {
            const uint32_t bs = bufa + sub * SUBSZ;
#pragma unroll
            for (int ks = 0; ks < 2; ks++) {
                const uint32_t kb = (uint32_t)ks * 32;   // bytes (16 halves)
                uint32_t ah[2][4], alf[2][4], bhf[4][2], blf[4][2];
#pragma unroll
                for (int mt = 0; mt < 2; mt++)
                    ldsm4(ah[mt], bs + ABUF_H + a_lm + mt * 16 * KROWB + kb);
#pragma unroll
                for (int ntp = 0; ntp < 2; ntp++) {
                    uint32_t r[4];
                    ldsm4(r, bs + BBUF_H + b_lm + ntp * 16 * KROWB + kb);
                    bhf[2*ntp][0] = r[0]; bhf[2*ntp+1][0] = r[1];
                    bhf[2*ntp][1] = r[2]; bhf[2*ntp+1][1] = r[3];
                }
#pragma unroll
                for (int mt = 0; mt < 2; mt++)
#pragma unroll
                    for (int nt = 0; nt < 4; nt++)
                        mma16816(acc[mt][nt], ah[mt], bhf[nt]);
#pragma unroll
                for (int ntp = 0; ntp < 2; ntp++) {
                    uint32_t r[4];
                    ldsm4(r, bs + BBUF_L + b_lm + ntp * 16 * KROWB + kb);
                    blf[2*ntp][0] = r[0]; blf[2*ntp+1][0] = r[1];
                    blf[2*ntp][1] = r[2]; blf[2*ntp+1][1] = r[3];
                }
#pragma unroll
                for (int mt = 0; mt < 2; mt++)
#pragma unroll
                    for (int nt = 0; nt < 4; nt++)
                        mma16816(acc[mt][nt], ah[mt], blf[nt]);
#pragma unroll
                for (int mt = 0; mt < 2; mt++)
                    ldsm4(alf[mt], bs + ABUF_L + a_lm + mt * 16 * KROWB + kb);
#pragma unroll
                for (int mt = 0; mt < 2; mt++)
#pragma unroll
                    for (int nt = 0; nt < 4; nt++)
                        mma16816(acc[mt][nt], alf[mt], bhf[nt]);
            }
        }
    }

    // ---- epilogue ----
#pragma unroll
    for (int nt = 0; nt < 4; nt++) {
        int c = n0 + cg * 32 + nt * 8 + tig * 2;
        float b0v = bias ? __ldg(bias + c) : 0.f;
        float b1v = bias ? __ldg(bias + c + 1) : 0.f;
#pragma unroll
        for (int mt = 0; mt < 2; mt++) {
            int r = r0 + rg * 32 + mt * 16 + group;
            if (r < M)
                *(float2*)(C + (size_t)r * 256 + c) =
                    make_float2(acc[mt][nt][0] + b0v, acc[mt][nt][1] + b1v);
            if (r + 8 < M)
                *(float2*)(C + (size_t)(r + 8) * 256 + c) =
                    make_float2(acc[mt][nt][2] + b0v, acc[mt][nt][3] + b1v);
        }
    }
#undef LDG_CHUNK
}

// ---------------- CSR build ------------------------------------------------
__global__ void deg_init_kernel(int* deg) {
    int i = blockIdx.x * blockDim.x + threadIdx.x;
    if (i < NN) deg[i] = 1;
}
__global__ void deg_count_kernel(const int* __restrict__ ei, int* deg) {
    int i = blockIdx.x * blockDim.x + threadIdx.x;
    if (i < EE) atomicAdd(&deg[ei[EE + i]], 1);
}

// --- 3-kernel coalesced scan ---
__global__ void scan_sum_kernel(const int* __restrict__ deg, int* __restrict__ bsum) {
    int i = blockIdx.x * 256 + threadIdx.x;
    int lane = threadIdx.x & 31, wid = threadIdx.x >> 5;
    int d = (i < NN) ? deg[i] : 0;
#pragma unroll
    for (int o = 16; o > 0; o >>= 1) d += __shfl_xor_sync(0xffffffffu, d, o);
    __shared__ int ws[8];
    if (lane == 0) ws[wid] = d;
    __syncthreads();
    if (threadIdx.x == 0) {
        int s = 0;
#pragma unroll
        for (int w = 0; w < 8; w++) s += ws[w];
        bsum[blockIdx.x] = s;
    }
}
__global__ void scan_top_kernel(int* __restrict__ bsum, int* __restrict__ off) {
    int t = threadIdx.x, lane = t & 31, wid = t >> 5;
    int v = (t < SCB) ? bsum[t] : 0;
    int x = v;
#pragma unroll
    for (int o = 1; o < 32; o <<= 1) {
        int y = __shfl_up_sync(0xffffffffu, x, o);
        if (lane >= o) x += y;
    }
    __shared__ int ws[8];
    if (lane == 31) ws[wid] = x;
    __syncthreads();
    int wpre = 0;
#pragma unroll
    for (int w = 0; w < 8; w++) if (w < wid) wpre += ws[w];
    int incl = x + wpre;
    if (t < SCB) bsum[t] = incl - v;
    if (t == 255) off[NN] = incl;
}
__global__ void scan_final_kernel(const int* __restrict__ deg,
                                  const int* __restrict__ bsum,
                                  int* __restrict__ off, int* __restrict__ pos) {
    int i = blockIdx.x * 256 + threadIdx.x;
    int lane = threadIdx.x & 31, wid = threadIdx.x >> 5;
    int d = (i < NN) ? deg[i] : 0;
    int x = d;
#pragma unroll
    for (int o = 1; o < 32; o <<= 1) {
        int y = __shfl_up_sync(0xffffffffu, x, o);
        if (lane >= o) x += y;
    }
    __shared__ int ws[8];
    if (lane == 31) ws[wid] = x;
    __syncthreads();
    int wpre = 0;
#pragma unroll
    for (int w = 0; w < 8; w++) if (w < wid) wpre += ws[w];
    int excl = x - d + wpre + bsum[blockIdx.x];
    if (i < NN) { off[i] = excl; pos[i] = excl; }
}

__global__ void csr_fill_kernel(const int* __restrict__ ei, int* pos, int* csr) {
    int i = blockIdx.x * blockDim.x + threadIdx.x;
    if (i >= ETOT) return;
    int s, d;
    if (i < EE) { s = ei[i]; d = ei[EE + i]; }
    else        { s = d = i - EE; }
    int p = atomicAdd(&pos[d], 1);
    csr[p] = s;
}

// ---------------- attention scores ----------------------------------------
template <int H, int C>
__global__ void scores_kernel(const float* __restrict__ h,
                              const float* __restrict__ asrc,
                              const float* __restrict__ adst,
                              float* __restrict__ ssrc, float* __restrict__ sdst)
{
    int gw = (blockIdx.x * blockDim.x + threadIdx.x) >> 5;
    if (gw >= NN) return;
    int lane = threadIdx.x & 31;

    const float4* hp = (const float4*)(h + gw * 256 + lane * 8);
    float4 v0 = hp[0], v1 = hp[1];
    const float4* ap = (const float4*)(asrc + lane * 8);
    float4 a0 = ap[0], a1 = ap[1];
    const float4* dp = (const float4*)(adst + lane * 8);
    float4 d0 = dp[0], d1 = dp[1];

    float ps = v0.x * a0.x + v0.y * a0.y + v0.z * a0.z + v0.w * a0.w +
               v1.x * a1.x + v1.y * a1.y + v1.z * a1.z + v1.w * a1.w;
    float pd = v0.x * d0.x + v0.y * d0.y + v0.z * d0.z + v0.w * d0.w +
               v1.x * d1.x + v1.y * d1.y + v1.z * d1.z + v1.w * d1.w;

    const int GC = C / 8;
#pragma unroll
    for (int o = 1; o < GC; o <<= 1) {
        ps += __shfl_xor_sync(0xffffffffu, ps, o);
        pd += __shfl_xor_sync(0xffffffffu, pd, o);
    }
    int myh = lane / GC;
    if ((lane & (GC - 1)) == 0) {
        ssrc[gw * H + myh] = ps;
        sdst[gw * H + myh] = pd;
    }
}

// ------- GAT aggregation fused with bias+elu+residual+LN (+ pooling) -------
template <int H, int C, bool POOL>
__global__ void agg_fused_kernel(const float* __restrict__ ssrc,
                                 const float* __restrict__ sdst,
                                 const float* __restrict__ h,
                                 const int* __restrict__ off,
                                 const int* __restrict__ csr,
                                 const float* __restrict__ bias,
                                 const float* __restrict__ xin,
                                 const float* __restrict__ g,
                                 const float* __restrict__ be,
                                 float* __restrict__ xout,
                                 const float* __restrict__ x0p,
                                 const int* __restrict__ batch,
                                 float* __restrict__ p2,
                                 float* __restrict__ p0,
                                 float* __restrict__ cnt)
{
    int gw = (blockIdx.x * blockDim.x + threadIdx.x) >> 5;
    if (gw >= NN) return;
    int lane = threadIdx.x & 31;

    int e0 = off[gw];
    int deg = off[gw + 1] - e0;

    const int ES = 32 / H;
    int hh = lane % H;
    int j0 = lane / H;

    float sd = __ldg(&sdst[gw * H + hh]);
    float m = -1e30f, z = 0.f;
    for (int j = j0; j < deg; j += ES) {
        int s = __ldg(&csr[e0 + j]);
        float e = __ldg(&ssrc[s * H + hh]) + sd;
        e = e > 0.f ? e : 0.2f * e;
        float mn = fmaxf(m, e);
        z = z * __expf(m - mn) + __expf(e - mn);
        m = mn;
    }
#pragma unroll
    for (int o = H; o < 32; o <<= 1) {
        float mo = __shfl_xor_sync(0xffffffffu, m, o);
        float zo = __shfl_xor_sync(0xffffffffu, z, o);
        float mn = fmaxf(m, mo);
        z = z * __expf(m - mn) + zo * __expf(mo - mn);
        m = mn;
    }

    const int myh = (lane * 8) / C;
    float my_m  = __shfl_sync(0xffffffffu, m, myh);
    float my_zi = 1.f / __shfl_sync(0xffffffffu, z, myh);
    float my_sd = __ldg(&sdst[gw * H + myh]);

    float acc[8] = {0.f, 0.f, 0.f, 0.f, 0.f, 0.f, 0.f, 0.f};
    for (int j = 0; j < deg; j++) {
        int s = __ldg(&csr[e0 + j]);
        float e = __ldg(&ssrc[s * H + myh]) + my_sd;
        e = e > 0.f ? e : 0.2f * e;
        float a = __expf(e - my_m) * my_zi;
        const float4* hp = (const float4*)(h + s * 256 + lane * 8);
        float4 v0 = __ldg(hp);
        float4 v1 = __ldg(hp + 1);
        acc[0] += a * v0.x; acc[1] += a * v0.y; acc[2] += a * v0.z; acc[3] += a * v0.w;
        acc[4] += a * v1.x; acc[5] += a * v1.y; acc[6] += a * v1.z; acc[7] += a * v1.w;
    }

    int base = gw * 256 + lane * 8;
    float4 b0 = *(const float4*)(bias + lane * 8);
    float4 b1 = *(const float4*)(bias + lane * 8 + 4);
    float4 x0v = *(const float4*)(xin + base);
    float4 x1v = *(const float4*)(xin + base + 4);
    float bb[8] = {b0.x, b0.y, b0.z, b0.w, b1.x, b1.y, b1.z, b1.w};
    float xv[8] = {x0v.x, x0v.y, x0v.z, x0v.w, x1v.x, x1v.y, x1v.z, x1v.w};

    float v[8];
    float sum = 0.f, sq = 0.f;
#pragma unroll
    for (int k = 0; k < 8; k++) {
        float t = acc[k] + bb[k];
        t = (t > 0.f) ? t : (__expf(t) - 1.f);
        t += xv[k];
        v[k] = t;
        sum += t;
        sq += t * t;
    }
#pragma unroll
    for (int o = 1; o < 32; o <<= 1) {
        sum += __shfl_xor_sync(0xffffffffu, sum, o);
        sq  += __shfl_xor_sync(0xffffffffu, sq, o);
    }
    float mean = sum * (1.f / 256.f);
    float var  = sq * (1.f / 256.f) - mean * mean;
    float rs   = rsqrtf(var + 1e-5f);

    float4 g0 = *(const float4*)(g + lane * 8);
    float4 g1 = *(const float4*)(g + lane * 8 + 4);
    float4 e0v = *(const float4*)(be + lane * 8);
    float4 e1v = *(const float4*)(be + lane * 8 + 4);
    float gv[8] = {g0.x, g0.y, g0.z, g0.w, g1.x, g1.y, g1.z, g1.w};
    float ev[8] = {e0v.x, e0v.y, e0v.z, e0v.w, e1v.x, e1v.y, e1v.z, e1v.w};

    float o0[8];
#pragma unroll
    for (int k = 0; k < 8; k++) o0[k] = (v[k] - mean) * rs * gv[k] + ev[k];

    if (!POOL) {
        *(float4*)(xout + base)     = make_float4(o0[0], o0[1], o0[2], o0[3]);
        *(float4*)(xout + base + 4) = make_float4(o0[4], o0[5], o0[6], o0[7]);
    } else {
        int b = __ldg(&batch[gw]);
        float* pp2 = p2 + b * 256 + lane * 8;
        float* pp0 = p0 + b * 256 + lane * 8;
        float4 z0 = *(const float4*)(x0p + base);
        float4 z1 = *(const float4*)(x0p + base + 4);
        float zv[8] = {z0.x, z0.y, z0.z, z0.w, z1.x, z1.y, z1.z, z1.w};
#pragma unroll
        for (int k = 0; k < 8; k++) {
            atomicAdd(pp2 + k, o0[k]);
            atomicAdd(pp0 + k, zv[k]);
        }
        if (lane == 0) atomicAdd(&cnt[b], 1.f);
    }
}

// ---------------- pooling init ---------------------------------------------
__global__ void pool_init_kernel(float* p2, float* p0, float* cnt) {
    int i = blockIdx.x * blockDim.x + threadIdx.x;
    if (i < BB * DD) { p2[i] = 0.f; p0[i] = 0.f; }
    if (i < BB) cnt[i] = 0.f;
}

// ---------------- classification head (block per graph) -------------------
__global__ void head_kernel(const float* __restrict__ p2,
                            const float* __restrict__ p0,
                            const float* __restrict__ cnt,
                            const float* __restrict__ Wf,  const float* __restrict__ bf,
                            const float* __restrict__ Wc1, const float* __restrict__ bc1,
                            const float* __restrict__ Wc2, const float* __restrict__ bc2,
                            float* __restrict__ out)
{
    __shared__ float xc[512];
    __shared__ float f[256];
    __shared__ float c1[128];
    __shared__ float lg[20];

    int b = blockIdx.x, t = threadIdx.x;
    float c = fmaxf(cnt[b], 1.f);
    xc[t]       = p2[b * 256 + t] / c;
    xc[256 + t] = p0[b * 256 + t] / c;
    __syncthreads();

    float acc = bf[t];
    for (int i = 0; i < 512; i++) acc += xc[i] * Wf[i * 256 + t];
    f[t] = fmaxf(acc, 0.f);
    __syncthreads();

    if (t < 128) {
        float a = bc1[t];
        for (int i = 0; i < 256; i++) a += f[i] * Wc1[i * 128 + t];
        c1[t] = fmaxf(a, 0.f);
    }
    __syncthreads();

    if (t < 20) {
        float a = bc2[t];
        for (int i = 0; i < 128; i++) a += c1[i] * Wc2[i * 20 + t];
        lg[t] = a;
    }
    __syncthreads();

    if (t < 32) {
        float v = (t < 20) ? lg[t] : -1e30f;
        float m = v;
#pragma unroll
        for (int o = 1; o < 32; o <<= 1) m = fmaxf(m, __shfl_xor_sync(0xffffffffu, m, o));
        float e = (t < 20) ? expf(v - m) : 0.f;
        float s = e;
#pragma unroll
        for (int o = 1; o < 32; o <<= 1) s += __shfl_xor_sync(0xffffffffu, s, o);
        if (t < 20) out[b * 20 + t] = v - m - logf(s);
    }
}

// ---------------- launcher -------------------------------------------------
extern "C" void kernel_launch(void* const* d_in, const int* in_sizes, int n_in,
                              void* d_out, int out_size)
{
    const float* x    = (const float*)d_in[0];
    const int*   ei   = (const int*)  d_in[1];
    const int*   batch= (const int*)  d_in[2];
    const float* W_in = (const float*)d_in[3];
    const float* b_in = (const float*)d_in[4];
    const float* W1   = (const float*)d_in[5];
    const float* as1  = (const float*)d_in[6];
    const float* ad1  = (const float*)d_in[7];
    const float* b1   = (const float*)d_in[8];
    const float* g1   = (const float*)d_in[9];
    const float* be1  = (const float*)d_in[10];
    const float* W2   = (const float*)d_in[11];
    const float* as2  = (const float*)d_in[12];
    const float* ad2  = (const float*)d_in[13];
    const float* b2   = (const float*)d_in[14];
    const float* g2   = (const float*)d_in[15];
    const float* be2  = (const float*)d_in[16];
    const float* Wf   = (const float*)d_in[17];
    const float* bfv  = (const float*)d_in[18];
    const float* Wc1  = (const float*)d_in[19];
    const float* bc1  = (const float*)d_in[20];
    const float* Wc2  = (const float*)d_in[21];
    const float* bc2  = (const float*)d_in[22];
    float* out = (float*)d_out;

    float *x0, *x1, *h, *ssrc, *sdst, *p2, *p0, *cnt;
    int *deg, *off, *pos, *csr, *bsum;
    __nv_bfloat16 *wbh, *wbl, *w1h, *w1l, *w2h, *w2l;
    cudaGetSymbolAddress((void**)&x0,  g_x0);
    cudaGetSymbolAddress((void**)&x1,  g_x1);
    cudaGetSymbolAddress((void**)&h,   g_h);
    cudaGetSymbolAddress((void**)&ssrc,g_ssrc);
    cudaGetSymbolAddress((void**)&sdst,g_sdst);
    cudaGetSymbolAddress((void**)&deg, g_deg);
    cudaGetSymbolAddress((void**)&off, g_off);
    cudaGetSymbolAddress((void**)&pos, g_pos);
    cudaGetSymbolAddress((void**)&csr, g_csr);
    cudaGetSymbolAddress((void**)&bsum,g_bsum);
    cudaGetSymbolAddress((void**)&p2,  g_p2);
    cudaGetSymbolAddress((void**)&p0,  g_p0);
    cudaGetSymbolAddress((void**)&cnt, g_cnt);
    cudaGetSymbolAddress((void**)&wbh, g_wbt_hi);
    cudaGetSymbolAddress((void**)&wbl, g_wbt_lo);
    cudaGetSymbolAddress((void**)&w1h, g_w1t_hi);
    cudaGetSymbolAddress((void**)&w1l, g_w1t_lo);
    cudaGetSymbolAddress((void**)&w2h, g_w2t_hi);
    cudaGetSymbolAddress((void**)&w2l, g_w2t_lo);

    cudaFuncSetAttribute(mm_mma_kernel, cudaFuncAttributeMaxDynamicSharedMemorySize, MM_SMEM);

    const int WARP_BLOCKS = NN / 8;
    const dim3 MMGRID((NN + 127) / 128, 2);   // 313 x 2

    // 0: big weight prep (coalesced transpose)
    wprep_kernel<<<dim3(KPBIG / 32, 8), 256>>>(W_in, wbh, wbl, KBIG, KPBIG);
    // 1-2: degree
    deg_init_kernel<<<(NN + 255) / 256, 256>>>(deg);
    deg_count_kernel<<<(EE + 255) / 256, 256>>>(ei, deg);
    // 3: BIG GEMM  <- ncu captures launch index 3
    mm_mma_kernel<<<MMGRID, 512, MM_SMEM>>>(x, wbh, wbl, b_in, x0, NN, KBIG, KPBIG);
    // 4-6: scan (coalesced, multi-block)
    scan_sum_kernel<<<SCB, 256>>>(deg, bsum);
    scan_top_kernel<<<1, 256>>>(bsum, off);
    scan_final_kernel<<<SCB, 256>>>(deg, bsum, off, pos);
    // 7: csr fill
    csr_fill_kernel<<<(ETOT + 255) / 256, 256>>>(ei, pos, csr);
    // conv weight preps
    wprep_kernel<<<dim3(256 / 32, 8), 256>>>(W1, w1h, w1l, 256, 256);
    wprep_kernel<<<dim3(256 / 32, 8), 256>>>(W2, w2h, w2l, 256, 256);

    // conv1
    mm_mma_kernel<<<MMGRID, 512, MM_SMEM>>>(x0, w1h, w1l, nullptr, h, NN, 256, 256);
    scores_kernel<8, 32><<<WARP_BLOCKS, 256>>>(h, as1, ad1, ssrc, sdst);
    agg_fused_kernel<8, 32, false><<<WARP_BLOCKS, 256>>>(
        ssrc, sdst, h, off, csr, b1, x0, g1, be1, x1,
        nullptr, nullptr, nullptr, nullptr, nullptr);

    // conv2 (+ fused pooling)
    mm_mma_kernel<<<MMGRID, 512, MM_SMEM>>>(x1, w2h, w2l, nullptr, h, NN, 256, 256);
    scores_kernel<4, 64><<<WARP_BLOCKS, 256>>>(h, as2, ad2, ssrc, sdst);
    pool_init_kernel<<<64, 256>>>(p2, p0, cnt);
    agg_fused_kernel<4, 64, true><<<WARP_BLOCKS, 256>>>(
        ssrc, sdst, h, off, csr, b2, x1, g2, be2, nullptr,
        x0, batch, p2, p0, cnt);

    // head
    head_kernel<<<BB, 256>>>(p2, p0, cnt, Wf, bfv, Wc1, bc1, Wc2, bc2, out);
}

// round 13
// speedup vs baseline: 2.2011x; 1.2657x over previous
#include <cuda_runtime.h>
#include <cuda_fp16.h>
#include <math.h>
#include <cstdint>

#define NN 40000
#define EE 1280000
#define ETOT (EE + NN)
#define DD 256
#define BB 64
#define NCLS 20
#define KBIG 5000
#define KPBIG 5056   /* 79 * 64 */
#define SCB 157      /* ceil(NN/256) scan blocks */

// ---------------- scratch (static device allocations) ----------------------
__device__ float g_x0[NN * DD];
__device__ float g_x1[NN * DD];
__device__ float g_h[NN * DD];
__device__ float g_ssrc[NN * 8];
__device__ float g_sdst[NN * 8];
__device__ int   g_deg[NN];
__device__ int   g_off[NN + 1];
__device__ int   g_pos[NN];
__device__ int   g_csr[ETOT];
__device__ int   g_bsum[256];
__device__ float g_p2[BB * DD];
__device__ float g_p0[BB * DD];
__device__ float g_cnt[BB];
__device__ __half g_wbt[256 * KPBIG];
__device__ __half g_w1t[256 * 256];
__device__ __half g_w2t[256 * 256];

__device__ __forceinline__ uint32_t smem_to_u32(const void* p) {
    uint32_t a;
    asm("{ .reg .u64 t; cvta.to.shared.u64 t, %1; cvt.u32.u64 %0, t; }"
        : "=r"(a) : "l"(p));
    return a;
}

__device__ __forceinline__ uint32_t h2pack(float a, float b) {
    __half2 t;
    t.x = __float2half_rn(a);
    t.y = __float2half_rn(b);
    return *reinterpret_cast<uint32_t*>(&t);
}

__device__ __forceinline__ void mma16816(float* c, const uint32_t* a, const uint32_t* b) {
    asm volatile(
        "mma.sync.aligned.m16n8k16.row.col.f32.f16.f16.f32 "
        "{%0,%1,%2,%3}, {%4,%5,%6,%7}, {%8,%9}, {%0,%1,%2,%3};"
        : "+f"(c[0]), "+f"(c[1]), "+f"(c[2]), "+f"(c[3])
        : "r"(a[0]), "r"(a[1]), "r"(a[2]), "r"(a[3]), "r"(b[0]), "r"(b[1]));
}

__device__ __forceinline__ void ldsm4(uint32_t* r, uint32_t addr) {
    asm volatile("ldmatrix.sync.aligned.m8n8.x4.shared.b16 {%0,%1,%2,%3}, [%4];"
        : "=r"(r[0]), "=r"(r[1]), "=r"(r[2]), "=r"(r[3]) : "r"(addr));
}

// ------- weight prep (coalesced transpose): W[K,256] -> Wt[256,KP] fp16 -----
__global__ void wprep_kernel(const float* __restrict__ W,
                             __half* __restrict__ th, int K, int KP)
{
    __shared__ float tile[32][33];
    const int kb = blockIdx.x * 32, nb = blockIdx.y * 32;
    const int tx = threadIdx.x & 31, ty = threadIdx.x >> 5;
#pragma unroll
    for (int r = ty; r < 32; r += 8) {
        int k = kb + r;
        tile[r][tx] = (k < K) ? __ldg(&W[(size_t)k * 256 + nb + tx]) : 0.f;
    }
    __syncthreads();
#pragma unroll
    for (int r = ty; r < 32; r += 8) {
        int n = nb + r, k = kb + tx;
        th[(size_t)n * KP + k] = __float2half_rn(tile[tx][r]);
    }
}

// -- mma.sync GEMM: fp16 2-pass (AhBh + AlBh), 512 thr, warp 32x32, K64 -----
#define KROWB 80
#define ABUF_H 0
#define ABUF_L 10240
#define BBUF_H 20480
#define SUBSZ  30720
#define BUFSZ  (2 * SUBSZ)      /* 61440: two 32-k sub-buffers */
#define MM_SMEM (2 * BUFSZ)     /* 122880 */

__global__ void __launch_bounds__(512, 1)
mm_mma_kernel(const float* __restrict__ A,
              const __half* __restrict__ Bh,
              const float* __restrict__ bias,
              float* __restrict__ C, int M, int Kdim, int KP)
{
    extern __shared__ char smem[];
    const uint32_t sb = smem_to_u32(smem);
    const int tid = threadIdx.x, wid = tid >> 5, lane = tid & 31;
    const int group = lane >> 2, tig = lane & 3;
    const int rg = wid >> 2, cg = wid & 3;          // 4 row-groups x 4 col-groups
    const int r0 = blockIdx.x * 128, n0 = blockIdx.y * 128;

    float acc[2][4][4];
#pragma unroll
    for (int mt = 0; mt < 2; mt++)
#pragma unroll
        for (int nt = 0; nt < 4; nt++)
#pragma unroll
            for (int j = 0; j < 4; j++) acc[mt][nt][j] = 0.f;

    const int NCH = KP >> 6;                 // 64-k chunks
    const int arow = tid >> 2;               // 0..127
    const int acol0 = (tid & 3) * 16;        // 0,16,32,48 (fp32 elements)
    const bool arok = (r0 + arow) < M;
    const float* Abase = A + (size_t)(r0 + arow) * Kdim;
    const int bn = tid >> 2, bseg = tid & 3; // B: 16 halves each

    float apf[16];
    uint4 bpfh[2];

#define LDG_CHUNK(K0) do {                                                   \
    _Pragma("unroll")                                                        \
    for (int ii = 0; ii < 4; ii++) {                                         \
        int c = (K0) + acol0 + ii * 4;                                       \
        float4 v = make_float4(0.f, 0.f, 0.f, 0.f);                          \
        if (arok) {                                                          \
            if (c + 3 < Kdim) v = *(const float4*)(Abase + c);               \
            else {                                                           \
                if (c     < Kdim) v.x = Abase[c];                            \
                if (c + 1 < Kdim) v.y = Abase[c + 1];                        \
                if (c + 2 < Kdim) v.z = Abase[c + 2];                        \
                if (c + 3 < Kdim) v.w = Abase[c + 3];                        \
            }                                                                \
        }                                                                    \
        apf[ii*4+0] = v.x; apf[ii*4+1] = v.y;                                \
        apf[ii*4+2] = v.z; apf[ii*4+3] = v.w;                                \
    }                                                                        \
    {                                                                        \
        size_t so = (size_t)(n0 + bn) * KP + (K0) + bseg * 16;               \
        bpfh[0] = *(const uint4*)(Bh + so);                                  \
        bpfh[1] = *(const uint4*)(Bh + so + 8);                              \
    }                                                                        \
} while (0)

    LDG_CHUNK(0);

    // ldmatrix per-lane base offsets
    const uint32_t a_lm = (uint32_t)(rg * 32 + (lane & 15)) * KROWB + (lane >> 4) * 16;
    const int bmat = lane >> 3, brow = lane & 7;
    const uint32_t b_lm = (uint32_t)(cg * 32 + (bmat & 1) * 8 + brow) * KROWB + (bmat >> 1) * 16;

    for (int i = 0; i < NCH; i++) {
        char* buf = smem + (size_t)(i & 1) * BUFSZ;
        const uint32_t bufa = sb + (uint32_t)(i & 1) * BUFSZ;

        // ---- STS: A fp32 -> fp16 hi/lo, B hi passthrough ----
        {
            uint32_t ph[8], pl[8];
#pragma unroll
            for (int j = 0; j < 8; j++) {
                float vx = apf[2 * j], vy = apf[2 * j + 1];
                float hx = __half2float(__float2half_rn(vx));
                float hy = __half2float(__float2half_rn(vy));
                ph[j] = h2pack(vx, vy);
                pl[j] = h2pack(vx - hx, vy - hy);
            }
            int asub = acol0 >> 5;                 // 0 or 1
            int kloc = acol0 & 31;                 // 0 or 16
            char* ab = buf + asub * SUBSZ + arow * KROWB + kloc * 2;
            *(uint4*)(ab + ABUF_H)      = make_uint4(ph[0], ph[1], ph[2], ph[3]);
            *(uint4*)(ab + ABUF_H + 16) = make_uint4(ph[4], ph[5], ph[6], ph[7]);
            *(uint4*)(ab + ABUF_L)      = make_uint4(pl[0], pl[1], pl[2], pl[3]);
            *(uint4*)(ab + ABUF_L + 16) = make_uint4(pl[4], pl[5], pl[6], pl[7]);
            int bsub = bseg >> 1;                  // 0 or 1
            int bkloc = (bseg & 1) * 16;           // halves
            char* bb = buf + bsub * SUBSZ + bn * KROWB + bkloc * 2;
            *(uint4*)(bb + BBUF_H)      = bpfh[0];
            *(uint4*)(bb + BBUF_H + 16) = bpfh[1];
        }
        __syncthreads();

        if (i + 1 < NCH) LDG_CHUNK((i + 1) << 6);

        // ---- compute: 2 sub-buffers x 2 k-steps x (hh, lh) ----
#pragma unroll
        for (int sub = 0; sub < 2; sub++) {
            const uint32_t bs = bufa + sub * SUBSZ;
#pragma unroll
            for (int ks = 0; ks < 2; ks++) {
                const uint32_t kb = (uint32_t)ks * 32;   // bytes (16 halves)
                uint32_t ah[2][4], alf[2][4], bhf[4][2];
#pragma unroll
                for (int mt = 0; mt < 2; mt++)
                    ldsm4(ah[mt], bs + ABUF_H + a_lm + mt * 16 * KROWB + kb);
#pragma unroll
                for (int ntp = 0; ntp < 2; ntp++) {
                    uint32_t r[4];
                    ldsm4(r, bs + BBUF_H + b_lm + ntp * 16 * KROWB + kb);
                    bhf[2*ntp][0] = r[0]; bhf[2*ntp+1][0] = r[1];
                    bhf[2*ntp][1] = r[2]; bhf[2*ntp+1][1] = r[3];
                }
#pragma unroll
                for (int mt = 0; mt < 2; mt++)
#pragma unroll
                    for (int nt = 0; nt < 4; nt++)
                        mma16816(acc[mt][nt], ah[mt], bhf[nt]);
#pragma unroll
                for (int mt = 0; mt < 2; mt++)
                    ldsm4(alf[mt], bs + ABUF_L + a_lm + mt * 16 * KROWB + kb);
#pragma unroll
                for (int mt = 0; mt < 2; mt++)
#pragma unroll
                    for (int nt = 0; nt < 4; nt++)
                        mma16816(acc[mt][nt], alf[mt], bhf[nt]);
            }
        }
    }

    // ---- epilogue ----
#pragma unroll
    for (int nt = 0; nt < 4; nt++) {
        int c = n0 + cg * 32 + nt * 8 + tig * 2;
        float b0v = bias ? __ldg(bias + c) : 0.f;
        float b1v = bias ? __ldg(bias + c + 1) : 0.f;
#pragma unroll
        for (int mt = 0; mt < 2; mt++) {
            int r = r0 + rg * 32 + mt * 16 + group;
            if (r < M)
                *(float2*)(C + (size_t)r * 256 + c) =
                    make_float2(acc[mt][nt][0] + b0v, acc[mt][nt][1] + b1v);
            if (r + 8 < M)
                *(float2*)(C + (size_t)(r + 8) * 256 + c) =
                    make_float2(acc[mt][nt][2] + b0v, acc[mt][nt][3] + b1v);
        }
    }
#undef LDG_CHUNK
}

// ---------------- CSR build ------------------------------------------------
__global__ void deg_init_kernel(int* deg) {
    int i = blockIdx.x * blockDim.x + threadIdx.x;
    if (i < NN) deg[i] = 1;
}
__global__ void deg_count_kernel(const int* __restrict__ ei, int* deg) {
    int i = blockIdx.x * blockDim.x + threadIdx.x;
    if (i < EE) atomicAdd(&deg[ei[EE + i]], 1);
}

// --- 3-kernel coalesced scan ---
__global__ void scan_sum_kernel(const int* __restrict__ deg, int* __restrict__ bsum) {
    int i = blockIdx.x * 256 + threadIdx.x;
    int lane = threadIdx.x & 31, wid = threadIdx.x >> 5;
    int d = (i < NN) ? deg[i] : 0;
#pragma unroll
    for (int o = 16; o > 0; o >>= 1) d += __shfl_xor_sync(0xffffffffu, d, o);
    __shared__ int ws[8];
    if (lane == 0) ws[wid] = d;
    __syncthreads();
    if (threadIdx.x == 0) {
        int s = 0;
#pragma unroll
        for (int w = 0; w < 8; w++) s += ws[w];
        bsum[blockIdx.x] = s;
    }
}
__global__ void scan_top_kernel(int* __restrict__ bsum, int* __restrict__ off) {
    int t = threadIdx.x, lane = t & 31, wid = t >> 5;
    int v = (t < SCB) ? bsum[t] : 0;
    int x = v;
#pragma unroll
    for (int o = 1; o < 32; o <<= 1) {
        int y = __shfl_up_sync(0xffffffffu, x, o);
        if (lane >= o) x += y;
    }
    __shared__ int ws[8];
    if (lane == 31) ws[wid] = x;
    __syncthreads();
    int wpre = 0;
#pragma unroll
    for (int w = 0; w < 8; w++) if (w < wid) wpre += ws[w];
    int incl = x + wpre;
    if (t < SCB) bsum[t] = incl - v;
    if (t == 255) off[NN] = incl;
}
__global__ void scan_final_kernel(const int* __restrict__ deg,
                                  const int* __restrict__ bsum,
                                  int* __restrict__ off, int* __restrict__ pos) {
    int i = blockIdx.x * 256 + threadIdx.x;
    int lane = threadIdx.x & 31, wid = threadIdx.x >> 5;
    int d = (i < NN) ? deg[i] : 0;
    int x = d;
#pragma unroll
    for (int o = 1; o < 32; o <<= 1) {
        int y = __shfl_up_sync(0xffffffffu, x, o);
        if (lane >= o) x += y;
    }
    __shared__ int ws[8];
    if (lane == 31) ws[wid] = x;
    __syncthreads();
    int wpre = 0;
#pragma unroll
    for (int w = 0; w < 8; w++) if (w < wid) wpre += ws[w];
    int excl = x - d + wpre + bsum[blockIdx.x];
    if (i < NN) { off[i] = excl; pos[i] = excl; }
}

__global__ void csr_fill_kernel(const int* __restrict__ ei, int* pos, int* csr) {
    int i = blockIdx.x * blockDim.x + threadIdx.x;
    if (i >= ETOT) return;
    int s, d;
    if (i < EE) { s = ei[i]; d = ei[EE + i]; }
    else        { s = d = i - EE; }
    int p = atomicAdd(&pos[d], 1);
    csr[p] = s;
}

// ---------------- attention scores ----------------------------------------
template <int H, int C>
__global__ void scores_kernel(const float* __restrict__ h,
                              const float* __restrict__ asrc,
                              const float* __restrict__ adst,
                              float* __restrict__ ssrc, float* __restrict__ sdst)
{
    int gw = (blockIdx.x * blockDim.x + threadIdx.x) >> 5;
    if (gw >= NN) return;
    int lane = threadIdx.x & 31;

    const float4* hp = (const float4*)(h + gw * 256 + lane * 8);
    float4 v0 = hp[0], v1 = hp[1];
    const float4* ap = (const float4*)(asrc + lane * 8);
    float4 a0 = ap[0], a1 = ap[1];
    const float4* dp = (const float4*)(adst + lane * 8);
    float4 d0 = dp[0], d1 = dp[1];

    float ps = v0.x * a0.x + v0.y * a0.y + v0.z * a0.z + v0.w * a0.w +
               v1.x * a1.x + v1.y * a1.y + v1.z * a1.z + v1.w * a1.w;
    float pd = v0.x * d0.x + v0.y * d0.y + v0.z * d0.z + v0.w * d0.w +
               v1.x * d1.x + v1.y * d1.y + v1.z * d1.z + v1.w * d1.w;

    const int GC = C / 8;
#pragma unroll
    for (int o = 1; o < GC; o <<= 1) {
        ps += __shfl_xor_sync(0xffffffffu, ps, o);
        pd += __shfl_xor_sync(0xffffffffu, pd, o);
    }
    int myh = lane / GC;
    if ((lane & (GC - 1)) == 0) {
        ssrc[gw * H + myh] = ps;
        sdst[gw * H + myh] = pd;
    }
}

// ------- GAT aggregation fused with bias+elu+residual+LN (+ pooling) -------
template <int H, int C, bool POOL>
__global__ void agg_fused_kernel(const float* __restrict__ ssrc,
                                 const float* __restrict__ sdst,
                                 const float* __restrict__ h,
                                 const int* __restrict__ off,
                                 const int* __restrict__ csr,
                                 const float* __restrict__ bias,
                                 const float* __restrict__ xin,
                                 const float* __restrict__ g,
                                 const float* __restrict__ be,
                                 float* __restrict__ xout,
                                 const float* __restrict__ x0p,
                                 const int* __restrict__ batch,
                                 float* __restrict__ p2,
                                 float* __restrict__ p0,
                                 float* __restrict__ cnt)
{
    int gw = (blockIdx.x * blockDim.x + threadIdx.x) >> 5;
    if (gw >= NN) return;
    int lane = threadIdx.x & 31;

    int e0 = off[gw];
    int deg = off[gw + 1] - e0;

    const int ES = 32 / H;
    int hh = lane % H;
    int j0 = lane / H;

    float sd = __ldg(&sdst[gw * H + hh]);
    float m = -1e30f, z = 0.f;
    for (int j = j0; j < deg; j += ES) {
        int s = __ldg(&csr[e0 + j]);
        float e = __ldg(&ssrc[s * H + hh]) + sd;
        e = e > 0.f ? e : 0.2f * e;
        float mn = fmaxf(m, e);
        z = z * __expf(m - mn) + __expf(e - mn);
        m = mn;
    }
#pragma unroll
    for (int o = H; o < 32; o <<= 1) {
        float mo = __shfl_xor_sync(0xffffffffu, m, o);
        float zo = __shfl_xor_sync(0xffffffffu, z, o);
        float mn = fmaxf(m, mo);
        z = z * __expf(m - mn) + zo * __expf(mo - mn);
        m = mn;
    }

    const int myh = (lane * 8) / C;
    float my_m  = __shfl_sync(0xffffffffu, m, myh);
    float my_zi = 1.f / __shfl_sync(0xffffffffu, z, myh);
    float my_sd = __ldg(&sdst[gw * H + myh]);

    float acc[8] = {0.f, 0.f, 0.f, 0.f, 0.f, 0.f, 0.f, 0.f};
    for (int j = 0; j < deg; j++) {
        int s = __ldg(&csr[e0 + j]);
        float e = __ldg(&ssrc[s * H + myh]) + my_sd;
        e = e > 0.f ? e : 0.2f * e;
        float a = __expf(e - my_m) * my_zi;
        const float4* hp = (const float4*)(h + s * 256 + lane * 8);
        float4 v0 = __ldg(hp);
        float4 v1 = __ldg(hp + 1);
        acc[0] += a * v0.x; acc[1] += a * v0.y; acc[2] += a * v0.z; acc[3] += a * v0.w;
        acc[4] += a * v1.x; acc[5] += a * v1.y; acc[6] += a * v1.z; acc[7] += a * v1.w;
    }

    int base = gw * 256 + lane * 8;
    float4 b0 = *(const float4*)(bias + lane * 8);
    float4 b1 = *(const float4*)(bias + lane * 8 + 4);
    float4 x0v = *(const float4*)(xin + base);
    float4 x1v = *(const float4*)(xin + base + 4);
    float bb[8] = {b0.x, b0.y, b0.z, b0.w, b1.x, b1.y, b1.z, b1.w};
    float xv[8] = {x0v.x, x0v.y, x0v.z, x0v.w, x1v.x, x1v.y, x1v.z, x1v.w};

    float v[8];
    float sum = 0.f, sq = 0.f;
#pragma unroll
    for (int k = 0; k < 8; k++) {
        float t = acc[k] + bb[k];
        t = (t > 0.f) ? t : (__expf(t) - 1.f);
        t += xv[k];
        v[k] = t;
        sum += t;
        sq += t * t;
    }
#pragma unroll
    for (int o = 1; o < 32; o <<= 1) {
        sum += __shfl_xor_sync(0xffffffffu, sum, o);
        sq  += __shfl_xor_sync(0xffffffffu, sq, o);
    }
    float mean = sum * (1.f / 256.f);
    float var  = sq * (1.f / 256.f) - mean * mean;
    float rs   = rsqrtf(var + 1e-5f);

    float4 g0 = *(const float4*)(g + lane * 8);
    float4 g1 = *(const float4*)(g + lane * 8 + 4);
    float4 e0v = *(const float4*)(be + lane * 8);
    float4 e1v = *(const float4*)(be + lane * 8 + 4);
    float gv[8] = {g0.x, g0.y, g0.z, g0.w, g1.x, g1.y, g1.z, g1.w};
    float ev[8] = {e0v.x, e0v.y, e0v.z, e0v.w, e1v.x, e1v.y, e1v.z, e1v.w};

    float o0[8];
#pragma unroll
    for (int k = 0; k < 8; k++) o0[k] = (v[k] - mean) * rs * gv[k] + ev[k];

    if (!POOL) {
        *(float4*)(xout + base)     = make_float4(o0[0], o0[1], o0[2], o0[3]);
        *(float4*)(xout + base + 4) = make_float4(o0[4], o0[5], o0[6], o0[7]);
    } else {
        int b = __ldg(&batch[gw]);
        float* pp2 = p2 + b * 256 + lane * 8;
        float* pp0 = p0 + b * 256 + lane * 8;
        float4 z0 = *(const float4*)(x0p + base);
        float4 z1 = *(const float4*)(x0p + base + 4);
        float zv[8] = {z0.x, z0.y, z0.z, z0.w, z1.x, z1.y, z1.z, z1.w};
#pragma unroll
        for (int k = 0; k < 8; k++) {
            atomicAdd(pp2 + k, o0[k]);
            atomicAdd(pp0 + k, zv[k]);
        }
        if (lane == 0) atomicAdd(&cnt[b], 1.f);
    }
}

// ---------------- pooling init ---------------------------------------------
__global__ void pool_init_kernel(float* p2, float* p0, float* cnt) {
    int i = blockIdx.x * blockDim.x + threadIdx.x;
    if (i < BB * DD) { p2[i] = 0.f; p0[i] = 0.f; }
    if (i < BB) cnt[i] = 0.f;
}

// ---------------- classification head (block per graph) -------------------
__global__ void head_kernel(const float* __restrict__ p2,
                            const float* __restrict__ p0,
                            const float* __restrict__ cnt,
                            const float* __restrict__ Wf,  const float* __restrict__ bf,
                            const float* __restrict__ Wc1, const float* __restrict__ bc1,
                            const float* __restrict__ Wc2, const float* __restrict__ bc2,
                            float* __restrict__ out)
{
    __shared__ float xc[512];
    __shared__ float f[256];
    __shared__ float c1[128];
    __shared__ float lg[20];

    int b = blockIdx.x, t = threadIdx.x;
    float c = fmaxf(cnt[b], 1.f);
    xc[t]       = p2[b * 256 + t] / c;
    xc[256 + t] = p0[b * 256 + t] / c;
    __syncthreads();

    float acc = bf[t];
    for (int i = 0; i < 512; i++) acc += xc[i] * Wf[i * 256 + t];
    f[t] = fmaxf(acc, 0.f);
    __syncthreads();

    if (t < 128) {
        float a = bc1[t];
        for (int i = 0; i < 256; i++) a += f[i] * Wc1[i * 128 + t];
        c1[t] = fmaxf(a, 0.f);
    }
    __syncthreads();

    if (t < 20) {
        float a = bc2[t];
        for (int i = 0; i < 128; i++) a += c1[i] * Wc2[i * 20 + t];
        lg[t] = a;
    }
    __syncthreads();

    if (t < 32) {
        float v = (t < 20) ? lg[t] : -1e30f;
        float m = v;
#pragma unroll
        for (int o = 1; o < 32; o <<= 1) m = fmaxf(m, __shfl_xor_sync(0xffffffffu, m, o));
        float e = (t < 20) ? expf(v - m) : 0.f;
        float s = e;
#pragma unroll
        for (int o = 1; o < 32; o <<= 1) s += __shfl_xor_sync(0xffffffffu, s, o);
        if (t < 20) out[b * 20 + t] = v - m - logf(s);
    }
}

// ---------------- launcher -------------------------------------------------
extern "C" void kernel_launch(void* const* d_in, const int* in_sizes, int n_in,
                              void* d_out, int out_size)
{
    const float* x    = (const float*)d_in[0];
    const int*   ei   = (const int*)  d_in[1];
    const int*   batch= (const int*)  d_in[2];
    const float* W_in = (const float*)d_in[3];
    const float* b_in = (const float*)d_in[4];
    const float* W1   = (const float*)d_in[5];
    const float* as1  = (const float*)d_in[6];
    const float* ad1  = (const float*)d_in[7];
    const float* b1   = (const float*)d_in[8];
    const float* g1   = (const float*)d_in[9];
    const float* be1  = (const float*)d_in[10];
    const float* W2   = (const float*)d_in[11];
    const float* as2  = (const float*)d_in[12];
    const float* ad2  = (const float*)d_in[13];
    const float* b2   = (const float*)d_in[14];
    const float* g2   = (const float*)d_in[15];
    const float* be2  = (const float*)d_in[16];
    const float* Wf   = (const float*)d_in[17];
    const float* bfv  = (const float*)d_in[18];
    const float* Wc1  = (const float*)d_in[19];
    const float* bc1  = (const float*)d_in[20];
    const float* Wc2  = (const float*)d_in[21];
    const float* bc2  = (const float*)d_in[22];
    float* out = (float*)d_out;

    float *x0, *x1, *h, *ssrc, *sdst, *p2, *p0, *cnt;
    int *deg, *off, *pos, *csr, *bsum;
    __half *wbt, *w1t, *w2t;
    cudaGetSymbolAddress((void**)&x0,  g_x0);
    cudaGetSymbolAddress((void**)&x1,  g_x1);
    cudaGetSymbolAddress((void**)&h,   g_h);
    cudaGetSymbolAddress((void**)&ssrc,g_ssrc);
    cudaGetSymbolAddress((void**)&sdst,g_sdst);
    cudaGetSymbolAddress((void**)&deg, g_deg);
    cudaGetSymbolAddress((void**)&off, g_off);
    cudaGetSymbolAddress((void**)&pos, g_pos);
    cudaGetSymbolAddress((void**)&csr, g_csr);
    cudaGetSymbolAddress((void**)&bsum,g_bsum);
    cudaGetSymbolAddress((void**)&p2,  g_p2);
    cudaGetSymbolAddress((void**)&p0,  g_p0);
    cudaGetSymbolAddress((void**)&cnt, g_cnt);
    cudaGetSymbolAddress((void**)&wbt, g_wbt);
    cudaGetSymbolAddress((void**)&w1t, g_w1t);
    cudaGetSymbolAddress((void**)&w2t, g_w2t);

    cudaFuncSetAttribute(mm_mma_kernel, cudaFuncAttributeMaxDynamicSharedMemorySize, MM_SMEM);

    const int WARP_BLOCKS = NN / 8;
    const dim3 MMGRID((NN + 127) / 128, 2);   // 313 x 2

    // 0: big weight prep (coalesced transpose, fp16)
    wprep_kernel<<<dim3(KPBIG / 32, 8), 256>>>(W_in, wbt, KBIG, KPBIG);
    // 1-2: degree
    deg_init_kernel<<<(NN + 255) / 256, 256>>>(deg);
    deg_count_kernel<<<(EE + 255) / 256, 256>>>(ei, deg);
    // 3: BIG GEMM  <- ncu captures launch index 3
    mm_mma_kernel<<<MMGRID, 512, MM_SMEM>>>(x, wbt, b_in, x0, NN, KBIG, KPBIG);
    // 4-6: scan (coalesced, multi-block)
    scan_sum_kernel<<<SCB, 256>>>(deg, bsum);
    scan_top_kernel<<<1, 256>>>(bsum, off);
    scan_final_kernel<<<SCB, 256>>>(deg, bsum, off, pos);
    // 7: csr fill
    csr_fill_kernel<<<(ETOT + 255) / 256, 256>>>(ei, pos, csr);
    // conv weight preps
    wprep_kernel<<<dim3(256 / 32, 8), 256>>>(W1, w1t, 256, 256);
    wprep_kernel<<<dim3(256 / 32, 8), 256>>>(W2, w2t, 256, 256);

    // conv1
    mm_mma_kernel<<<MMGRID, 512, MM_SMEM>>>(x0, w1t, nullptr, h, NN, 256, 256);
    scores_kernel<8, 32><<<WARP_BLOCKS, 256>>>(h, as1, ad1, ssrc, sdst);
    agg_fused_kernel<8, 32, false><<<WARP_BLOCKS, 256>>>(
        ssrc, sdst, h, off, csr, b1, x0, g1, be1, x1,
        nullptr, nullptr, nullptr, nullptr, nullptr);

    // conv2 (+ fused pooling)
    mm_mma_kernel<<<MMGRID, 512, MM_SMEM>>>(x1, w2t, nullptr, h, NN, 256, 256);
    scores_kernel<4, 64><<<WARP_BLOCKS, 256>>>(h, as2, ad2, ssrc, sdst);
    pool_init_kernel<<<64, 256>>>(p2, p0, cnt);
    agg_fused_kernel<4, 64, true><<<WARP_BLOCKS, 256>>>(
        ssrc, sdst, h, off, csr, b2, x1, g2, be2, nullptr,
        x0, batch, p2, p0, cnt);

    // head
    head_kernel<<<BB, 256>>>(p2, p0, cnt, Wf, bfv, Wc1, bc1, Wc2, bc2, out);
}

// round 14
// speedup vs baseline: 2.4127x; 1.0961x over previous
#include <cuda_runtime.h>
#include <cuda_fp16.h>
#include <math.h>
#include <cstdint>

#define NN 40000
#define EE 1280000
#define ETOT (EE + NN)
#define DD 256
#define BB 64
#define NCLS 20
#define KBIG 5000
#define KPBIG 5056   /* 79 * 64 */
#define SCB 157      /* ceil(NN/256) scan blocks */

// ---------------- scratch (static device allocations) ----------------------
__device__ float g_x0[NN * DD];
__device__ float g_x1[NN * DD];
__device__ float g_h[NN * DD];
__device__ float g_ssrc[NN * 8];
__device__ float g_sdst[NN * 8];
__device__ int   g_deg[NN];
__device__ int   g_off[NN + 1];
__device__ int   g_pos[NN];
__device__ int   g_csr[ETOT];
__device__ int   g_bsum[256];
__device__ float g_p2[BB * DD];
__device__ float g_p0[BB * DD];
__device__ float g_cnt[BB];
__device__ __half g_wbt[256 * KPBIG];
__device__ __half g_w1t[256 * 256];
__device__ __half g_w2t[256 * 256];

__device__ __forceinline__ uint32_t smem_to_u32(const void* p) {
    uint32_t a;
    asm("{ .reg .u64 t; cvta.to.shared.u64 t, %1; cvt.u32.u64 %0, t; }"
        : "=r"(a) : "l"(p));
    return a;
}

__device__ __forceinline__ uint32_t h2pack(float a, float b) {
    __half2 t;
    t.x = __float2half_rn(a);
    t.y = __float2half_rn(b);
    return *reinterpret_cast<uint32_t*>(&t);
}

__device__ __forceinline__ void mma16816(float* c, const uint32_t* a, const uint32_t* b) {
    asm volatile(
        "mma.sync.aligned.m16n8k16.row.col.f32.f16.f16.f32 "
        "{%0,%1,%2,%3}, {%4,%5,%6,%7}, {%8,%9}, {%0,%1,%2,%3};"
        : "+f"(c[0]), "+f"(c[1]), "+f"(c[2]), "+f"(c[3])
        : "r"(a[0]), "r"(a[1]), "r"(a[2]), "r"(a[3]), "r"(b[0]), "r"(b[1]));
}

__device__ __forceinline__ void ldsm4(uint32_t* r, uint32_t addr) {
    asm volatile("ldmatrix.sync.aligned.m8n8.x4.shared.b16 {%0,%1,%2,%3}, [%4];"
        : "=r"(r[0]), "=r"(r[1]), "=r"(r[2]), "=r"(r[3]) : "r"(addr));
}

// ------- weight prep (coalesced transpose): W[K,256] -> Wt[256,KP] fp16 -----
__global__ void wprep_kernel(const float* __restrict__ W,
                             __half* __restrict__ th, int K, int KP)
{
    __shared__ float tile[32][33];
    const int kb = blockIdx.x * 32, nb = blockIdx.y * 32;
    const int tx = threadIdx.x & 31, ty = threadIdx.x >> 5;
#pragma unroll
    for (int r = ty; r < 32; r += 8) {
        int k = kb + r;
        tile[r][tx] = (k < K) ? __ldg(&W[(size_t)k * 256 + nb + tx]) : 0.f;
    }
    __syncthreads();
#pragma unroll
    for (int r = ty; r < 32; r += 8) {
        int n = nb + r, k = kb + tx;
        th[(size_t)n * KP + k] = __float2half_rn(tile[tx][r]);
    }
}

// -- mma.sync GEMM: pure fp16 1-pass, 512 thr, warp 32x32, K-chunk 64 -------
#define KROWB 80
#define ABUF_H 0
#define BBUF_H 10240
#define SUBSZ  20480
#define BUFSZ  (2 * SUBSZ)      /* 40960: two 32-k sub-buffers */
#define MM_SMEM (2 * BUFSZ)     /* 81920 */

__global__ void __launch_bounds__(512, 1)
mm_mma_kernel(const float* __restrict__ A,
              const __half* __restrict__ Bh,
              const float* __restrict__ bias,
              float* __restrict__ C, int M, int Kdim, int KP)
{
    extern __shared__ char smem[];
    const uint32_t sb = smem_to_u32(smem);
    const int tid = threadIdx.x, wid = tid >> 5, lane = tid & 31;
    const int group = lane >> 2, tig = lane & 3;
    const int rg = wid >> 2, cg = wid & 3;          // 4 row-groups x 4 col-groups
    const int r0 = blockIdx.x * 128, n0 = blockIdx.y * 128;

    float acc[2][4][4];
#pragma unroll
    for (int mt = 0; mt < 2; mt++)
#pragma unroll
        for (int nt = 0; nt < 4; nt++)
#pragma unroll
            for (int j = 0; j < 4; j++) acc[mt][nt][j] = 0.f;

    const int NCH = KP >> 6;                 // 64-k chunks
    const int arow = tid >> 2;               // 0..127
    const int acol0 = (tid & 3) * 16;        // 0,16,32,48 (fp32 elements)
    const bool arok = (r0 + arow) < M;
    const float* Abase = A + (size_t)(r0 + arow) * Kdim;
    const int bn = tid >> 2, bseg = tid & 3; // B: 16 halves each

    float apf[16];
    uint4 bpfh[2];

#define LDG_CHUNK(K0) do {                                                   \
    _Pragma("unroll")                                                        \
    for (int ii = 0; ii < 4; ii++) {                                         \
        int c = (K0) + acol0 + ii * 4;                                       \
        float4 v = make_float4(0.f, 0.f, 0.f, 0.f);                          \
        if (arok) {                                                          \
            if (c + 3 < Kdim) v = *(const float4*)(Abase + c);               \
            else {                                                           \
                if (c     < Kdim) v.x = Abase[c];                            \
                if (c + 1 < Kdim) v.y = Abase[c + 1];                        \
                if (c + 2 < Kdim) v.z = Abase[c + 2];                        \
                if (c + 3 < Kdim) v.w = Abase[c + 3];                        \
            }                                                                \
        }                                                                    \
        apf[ii*4+0] = v.x; apf[ii*4+1] = v.y;                                \
        apf[ii*4+2] = v.z; apf[ii*4+3] = v.w;                                \
    }                                                                        \
    {                                                                        \
        size_t so = (size_t)(n0 + bn) * KP + (K0) + bseg * 16;               \
        bpfh[0] = *(const uint4*)(Bh + so);                                  \
        bpfh[1] = *(const uint4*)(Bh + so + 8);                              \
    }                                                                        \
} while (0)

    LDG_CHUNK(0);

    // ldmatrix per-lane base offsets
    const uint32_t a_lm = (uint32_t)(rg * 32 + (lane & 15)) * KROWB + (lane >> 4) * 16;
    const int bmat = lane >> 3, brow = lane & 7;
    const uint32_t b_lm = (uint32_t)(cg * 32 + (bmat & 1) * 8 + brow) * KROWB + (bmat >> 1) * 16;

    for (int i = 0; i < NCH; i++) {
        char* buf = smem + (size_t)(i & 1) * BUFSZ;
        const uint32_t bufa = sb + (uint32_t)(i & 1) * BUFSZ;

        // ---- STS: A fp32 -> fp16, B passthrough; into 2 sub-buffers ----
        {
            uint32_t ph[8];
#pragma unroll
            for (int j = 0; j < 8; j++)
                ph[j] = h2pack(apf[2 * j], apf[2 * j + 1]);
            int asub = acol0 >> 5;                 // 0 or 1
            int kloc = acol0 & 31;                 // 0 or 16
            char* ab = buf + asub * SUBSZ + arow * KROWB + kloc * 2;
            *(uint4*)(ab + ABUF_H)      = make_uint4(ph[0], ph[1], ph[2], ph[3]);
            *(uint4*)(ab + ABUF_H + 16) = make_uint4(ph[4], ph[5], ph[6], ph[7]);
            int bsub = bseg >> 1;                  // 0 or 1
            int bkloc = (bseg & 1) * 16;           // halves
            char* bb = buf + bsub * SUBSZ + bn * KROWB + bkloc * 2;
            *(uint4*)(bb + BBUF_H)      = bpfh[0];
            *(uint4*)(bb + BBUF_H + 16) = bpfh[1];
        }
        __syncthreads();

        if (i + 1 < NCH) LDG_CHUNK((i + 1) << 6);

        // ---- compute: 2 sub-buffers x 2 k-steps, single pass ----
#pragma unroll
        for (int sub = 0; sub < 2; sub++) {
            const uint32_t bs = bufa + sub * SUBSZ;
#pragma unroll
            for (int ks = 0; ks < 2; ks++) {
                const uint32_t kb = (uint32_t)ks * 32;   // bytes (16 halves)
                uint32_t ah[2][4], bhf[4][2];
#pragma unroll
                for (int mt = 0; mt < 2; mt++)
                    ldsm4(ah[mt], bs + ABUF_H + a_lm + mt * 16 * KROWB + kb);
#pragma unroll
                for (int ntp = 0; ntp < 2; ntp++) {
                    uint32_t r[4];
                    ldsm4(r, bs + BBUF_H + b_lm + ntp * 16 * KROWB + kb);
                    bhf[2*ntp][0] = r[0]; bhf[2*ntp+1][0] = r[1];
                    bhf[2*ntp][1] = r[2]; bhf[2*ntp+1][1] = r[3];
                }
#pragma unroll
                for (int mt = 0; mt < 2; mt++)
#pragma unroll
                    for (int nt = 0; nt < 4; nt++)
                        mma16816(acc[mt][nt], ah[mt], bhf[nt]);
            }
        }
    }

    // ---- epilogue ----
#pragma unroll
    for (int nt = 0; nt < 4; nt++) {
        int c = n0 + cg * 32 + nt * 8 + tig * 2;
        float b0v = bias ? __ldg(bias + c) : 0.f;
        float b1v = bias ? __ldg(bias + c + 1) : 0.f;
#pragma unroll
        for (int mt = 0; mt < 2; mt++) {
            int r = r0 + rg * 32 + mt * 16 + group;
            if (r < M)
                *(float2*)(C + (size_t)r * 256 + c) =
                    make_float2(acc[mt][nt][0] + b0v, acc[mt][nt][1] + b1v);
            if (r + 8 < M)
                *(float2*)(C + (size_t)(r + 8) * 256 + c) =
                    make_float2(acc[mt][nt][2] + b0v, acc[mt][nt][3] + b1v);
        }
    }
#undef LDG_CHUNK
}

// ---------------- CSR build ------------------------------------------------
__global__ void deg_init_kernel(int* deg) {
    int i = blockIdx.x * blockDim.x + threadIdx.x;
    if (i < NN) deg[i] = 1;
}
__global__ void deg_count_kernel(const int* __restrict__ ei, int* deg) {
    int i = blockIdx.x * blockDim.x + threadIdx.x;
    if (i < EE) atomicAdd(&deg[ei[EE + i]], 1);
}

// --- 3-kernel coalesced scan ---
__global__ void scan_sum_kernel(const int* __restrict__ deg, int* __restrict__ bsum) {
    int i = blockIdx.x * 256 + threadIdx.x;
    int lane = threadIdx.x & 31, wid = threadIdx.x >> 5;
    int d = (i < NN) ? deg[i] : 0;
#pragma unroll
    for (int o = 16; o > 0; o >>= 1) d += __shfl_xor_sync(0xffffffffu, d, o);
    __shared__ int ws[8];
    if (lane == 0) ws[wid] = d;
    __syncthreads();
    if (threadIdx.x == 0) {
        int s = 0;
#pragma unroll
        for (int w = 0; w < 8; w++) s += ws[w];
        bsum[blockIdx.x] = s;
    }
}
__global__ void scan_top_kernel(int* __restrict__ bsum, int* __restrict__ off) {
    int t = threadIdx.x, lane = t & 31, wid = t >> 5;
    int v = (t < SCB) ? bsum[t] : 0;
    int x = v;
#pragma unroll
    for (int o = 1; o < 32; o <<= 1) {
        int y = __shfl_up_sync(0xffffffffu, x, o);
        if (lane >= o) x += y;
    }
    __shared__ int ws[8];
    if (lane == 31) ws[wid] = x;
    __syncthreads();
    int wpre = 0;
#pragma unroll
    for (int w = 0; w < 8; w++) if (w < wid) wpre += ws[w];
    int incl = x + wpre;
    if (t < SCB) bsum[t] = incl - v;
    if (t == 255) off[NN] = incl;
}
__global__ void scan_final_kernel(const int* __restrict__ deg,
                                  const int* __restrict__ bsum,
                                  int* __restrict__ off, int* __restrict__ pos) {
    int i = blockIdx.x * 256 + threadIdx.x;
    int lane = threadIdx.x & 31, wid = threadIdx.x >> 5;
    int d = (i < NN) ? deg[i] : 0;
    int x = d;
#pragma unroll
    for (int o = 1; o < 32; o <<= 1) {
        int y = __shfl_up_sync(0xffffffffu, x, o);
        if (lane >= o) x += y;
    }
    __shared__ int ws[8];
    if (lane == 31) ws[wid] = x;
    __syncthreads();
    int wpre = 0;
#pragma unroll
    for (int w = 0; w < 8; w++) if (w < wid) wpre += ws[w];
    int excl = x - d + wpre + bsum[blockIdx.x];
    if (i < NN) { off[i] = excl; pos[i] = excl; }
}

__global__ void csr_fill_kernel(const int* __restrict__ ei, int* pos, int* csr) {
    int i = blockIdx.x * blockDim.x + threadIdx.x;
    if (i >= ETOT) return;
    int s, d;
    if (i < EE) { s = ei[i]; d = ei[EE + i]; }
    else        { s = d = i - EE; }
    int p = atomicAdd(&pos[d], 1);
    csr[p] = s;
}

// ---------------- attention scores ----------------------------------------
template <int H, int C>
__global__ void scores_kernel(const float* __restrict__ h,
                              const float* __restrict__ asrc,
                              const float* __restrict__ adst,
                              float* __restrict__ ssrc, float* __restrict__ sdst)
{
    int gw = (blockIdx.x * blockDim.x + threadIdx.x) >> 5;
    if (gw >= NN) return;
    int lane = threadIdx.x & 31;

    const float4* hp = (const float4*)(h + gw * 256 + lane * 8);
    float4 v0 = hp[0], v1 = hp[1];
    const float4* ap = (const float4*)(asrc + lane * 8);
    float4 a0 = ap[0], a1 = ap[1];
    const float4* dp = (const float4*)(adst + lane * 8);
    float4 d0 = dp[0], d1 = dp[1];

    float ps = v0.x * a0.x + v0.y * a0.y + v0.z * a0.z + v0.w * a0.w +
               v1.x * a1.x + v1.y * a1.y + v1.z * a1.z + v1.w * a1.w;
    float pd = v0.x * d0.x + v0.y * d0.y + v0.z * d0.z + v0.w * d0.w +
               v1.x * d1.x + v1.y * d1.y + v1.z * d1.z + v1.w * d1.w;

    const int GC = C / 8;
#pragma unroll
    for (int o = 1; o < GC; o <<= 1) {
        ps += __shfl_xor_sync(0xffffffffu, ps, o);
        pd += __shfl_xor_sync(0xffffffffu, pd, o);
    }
    int myh = lane / GC;
    if ((lane & (GC - 1)) == 0) {
        ssrc[gw * H + myh] = ps;
        sdst[gw * H + myh] = pd;
    }
}

// ------- GAT aggregation fused with bias+elu+residual+LN (+ pooling) -------
template <int H, int C, bool POOL>
__global__ void agg_fused_kernel(const float* __restrict__ ssrc,
                                 const float* __restrict__ sdst,
                                 const float* __restrict__ h,
                                 const int* __restrict__ off,
                                 const int* __restrict__ csr,
                                 const float* __restrict__ bias,
                                 const float* __restrict__ xin,
                                 const float* __restrict__ g,
                                 const float* __restrict__ be,
                                 float* __restrict__ xout,
                                 const float* __restrict__ x0p,
                                 const int* __restrict__ batch,
                                 float* __restrict__ p2,
                                 float* __restrict__ p0,
                                 float* __restrict__ cnt)
{
    int gw = (blockIdx.x * blockDim.x + threadIdx.x) >> 5;
    if (gw >= NN) return;
    int lane = threadIdx.x & 31;

    int e0 = off[gw];
    int deg = off[gw + 1] - e0;

    const int ES = 32 / H;
    int hh = lane % H;
    int j0 = lane / H;

    float sd = __ldg(&sdst[gw * H + hh]);
    float m = -1e30f, z = 0.f;
    for (int j = j0; j < deg; j += ES) {
        int s = __ldg(&csr[e0 + j]);
        float e = __ldg(&ssrc[s * H + hh]) + sd;
        e = e > 0.f ? e : 0.2f * e;
        float mn = fmaxf(m, e);
        z = z * __expf(m - mn) + __expf(e - mn);
        m = mn;
    }
#pragma unroll
    for (int o = H; o < 32; o <<= 1) {
        float mo = __shfl_xor_sync(0xffffffffu, m, o);
        float zo = __shfl_xor_sync(0xffffffffu, z, o);
        float mn = fmaxf(m, mo);
        z = z * __expf(m - mn) + zo * __expf(mo - mn);
        m = mn;
    }

    const int myh = (lane * 8) / C;
    float my_m  = __shfl_sync(0xffffffffu, m, myh);
    float my_zi = 1.f / __shfl_sync(0xffffffffu, z, myh);
    float my_sd = __ldg(&sdst[gw * H + myh]);

    float acc[8] = {0.f, 0.f, 0.f, 0.f, 0.f, 0.f, 0.f, 0.f};
    for (int j = 0; j < deg; j++) {
        int s = __ldg(&csr[e0 + j]);
        float e = __ldg(&ssrc[s * H + myh]) + my_sd;
        e = e > 0.f ? e : 0.2f * e;
        float a = __expf(e - my_m) * my_zi;
        const float4* hp = (const float4*)(h + s * 256 + lane * 8);
        float4 v0 = __ldg(hp);
        float4 v1 = __ldg(hp + 1);
        acc[0] += a * v0.x; acc[1] += a * v0.y; acc[2] += a * v0.z; acc[3] += a * v0.w;
        acc[4] += a * v1.x; acc[5] += a * v1.y; acc[6] += a * v1.z; acc[7] += a * v1.w;
    }

    int base = gw * 256 + lane * 8;
    float4 b0 = *(const float4*)(bias + lane * 8);
    float4 b1 = *(const float4*)(bias + lane * 8 + 4);
    float4 x0v = *(const float4*)(xin + base);
    float4 x1v = *(const float4*)(xin + base + 4);
    float bb[8] = {b0.x, b0.y, b0.z, b0.w, b1.x, b1.y, b1.z, b1.w};
    float xv[8] = {x0v.x, x0v.y, x0v.z, x0v.w, x1v.x, x1v.y, x1v.z, x1v.w};

    float v[8];
    float sum = 0.f, sq = 0.f;
#pragma unroll
    for (int k = 0; k < 8; k++) {
        float t = acc[k] + bb[k];
        t = (t > 0.f) ? t : (__expf(t) - 1.f);
        t += xv[k];
        v[k] = t;
        sum += t;
        sq += t * t;
    }
#pragma unroll
    for (int o = 1; o < 32; o <<= 1) {
        sum += __shfl_xor_sync(0xffffffffu, sum, o);
        sq  += __shfl_xor_sync(0xffffffffu, sq, o);
    }
    float mean = sum * (1.f / 256.f);
    float var  = sq * (1.f / 256.f) - mean * mean;
    float rs   = rsqrtf(var + 1e-5f);

    float4 g0 = *(const float4*)(g + lane * 8);
    float4 g1 = *(const float4*)(g + lane * 8 + 4);
    float4 e0v = *(const float4*)(be + lane * 8);
    float4 e1v = *(const float4*)(be + lane * 8 + 4);
    float gv[8] = {g0.x, g0.y, g0.z, g0.w, g1.x, g1.y, g1.z, g1.w};
    float ev[8] = {e0v.x, e0v.y, e0v.z, e0v.w, e1v.x, e1v.y, e1v.z, e1v.w};

    float o0[8];
#pragma unroll
    for (int k = 0; k < 8; k++) o0[k] = (v[k] - mean) * rs * gv[k] + ev[k];

    if (!POOL) {
        *(float4*)(xout + base)     = make_float4(o0[0], o0[1], o0[2], o0[3]);
        *(float4*)(xout + base + 4) = make_float4(o0[4], o0[5], o0[6], o0[7]);
    } else {
        int b = __ldg(&batch[gw]);
        float* pp2 = p2 + b * 256 + lane * 8;
        float* pp0 = p0 + b * 256 + lane * 8;
        float4 z0 = *(const float4*)(x0p + base);
        float4 z1 = *(const float4*)(x0p + base + 4);
        float zv[8] = {z0.x, z0.y, z0.z, z0.w, z1.x, z1.y, z1.z, z1.w};
#pragma unroll
        for (int k = 0; k < 8; k++) {
            atomicAdd(pp2 + k, o0[k]);
            atomicAdd(pp0 + k, zv[k]);
        }
        if (lane == 0) atomicAdd(&cnt[b], 1.f);
    }
}

// ---------------- pooling init ---------------------------------------------
__global__ void pool_init_kernel(float* p2, float* p0, float* cnt) {
    int i = blockIdx.x * blockDim.x + threadIdx.x;
    if (i < BB * DD) { p2[i] = 0.f; p0[i] = 0.f; }
    if (i < BB) cnt[i] = 0.f;
}

// ---------------- classification head (block per graph) -------------------
__global__ void head_kernel(const float* __restrict__ p2,
                            const float* __restrict__ p0,
                            const float* __restrict__ cnt,
                            const float* __restrict__ Wf,  const float* __restrict__ bf,
                            const float* __restrict__ Wc1, const float* __restrict__ bc1,
                            const float* __restrict__ Wc2, const float* __restrict__ bc2,
                            float* __restrict__ out)
{
    __shared__ float xc[512];
    __shared__ float f[256];
    __shared__ float c1[128];
    __shared__ float lg[20];

    int b = blockIdx.x, t = threadIdx.x;
    float c = fmaxf(cnt[b], 1.f);
    xc[t]       = p2[b * 256 + t] / c;
    xc[256 + t] = p0[b * 256 + t] / c;
    __syncthreads();

    float acc = bf[t];
    for (int i = 0; i < 512; i++) acc += xc[i] * Wf[i * 256 + t];
    f[t] = fmaxf(acc, 0.f);
    __syncthreads();

    if (t < 128) {
        float a = bc1[t];
        for (int i = 0; i < 256; i++) a += f[i] * Wc1[i * 128 + t];
        c1[t] = fmaxf(a, 0.f);
    }
    __syncthreads();

    if (t < 20) {
        float a = bc2[t];
        for (int i = 0; i < 128; i++) a += c1[i] * Wc2[i * 20 + t];
        lg[t] = a;
    }
    __syncthreads();

    if (t < 32) {
        float v = (t < 20) ? lg[t] : -1e30f;
        float m = v;
#pragma unroll
        for (int o = 1; o < 32; o <<= 1) m = fmaxf(m, __shfl_xor_sync(0xffffffffu, m, o));
        float e = (t < 20) ? expf(v - m) : 0.f;
        float s = e;
#pragma unroll
        for (int o = 1; o < 32; o <<= 1) s += __shfl_xor_sync(0xffffffffu, s, o);
        if (t < 20) out[b * 20 + t] = v - m - logf(s);
    }
}

// ---------------- launcher -------------------------------------------------
extern "C" void kernel_launch(void* const* d_in, const int* in_sizes, int n_in,
                              void* d_out, int out_size)
{
    const float* x    = (const float*)d_in[0];
    const int*   ei   = (const int*)  d_in[1];
    const int*   batch= (const int*)  d_in[2];
    const float* W_in = (const float*)d_in[3];
    const float* b_in = (const float*)d_in[4];
    const float* W1   = (const float*)d_in[5];
    const float* as1  = (const float*)d_in[6];
    const float* ad1  = (const float*)d_in[7];
    const float* b1   = (const float*)d_in[8];
    const float* g1   = (const float*)d_in[9];
    const float* be1  = (const float*)d_in[10];
    const float* W2   = (const float*)d_in[11];
    const float* as2  = (const float*)d_in[12];
    const float* ad2  = (const float*)d_in[13];
    const float* b2   = (const float*)d_in[14];
    const float* g2   = (const float*)d_in[15];
    const float* be2  = (const float*)d_in[16];
    const float* Wf   = (const float*)d_in[17];
    const float* bfv  = (const float*)d_in[18];
    const float* Wc1  = (const float*)d_in[19];
    const float* bc1  = (const float*)d_in[20];
    const float* Wc2  = (const float*)d_in[21];
    const float* bc2  = (const float*)d_in[22];
    float* out = (float*)d_out;

    float *x0, *x1, *h, *ssrc, *sdst, *p2, *p0, *cnt;
    int *deg, *off, *pos, *csr, *bsum;
    __half *wbt, *w1t, *w2t;
    cudaGetSymbolAddress((void**)&x0,  g_x0);
    cudaGetSymbolAddress((void**)&x1,  g_x1);
    cudaGetSymbolAddress((void**)&h,   g_h);
    cudaGetSymbolAddress((void**)&ssrc,g_ssrc);
    cudaGetSymbolAddress((void**)&sdst,g_sdst);
    cudaGetSymbolAddress((void**)&deg, g_deg);
    cudaGetSymbolAddress((void**)&off, g_off);
    cudaGetSymbolAddress((void**)&pos, g_pos);
    cudaGetSymbolAddress((void**)&csr, g_csr);
    cudaGetSymbolAddress((void**)&bsum,g_bsum);
    cudaGetSymbolAddress((void**)&p2,  g_p2);
    cudaGetSymbolAddress((void**)&p0,  g_p0);
    cudaGetSymbolAddress((void**)&cnt, g_cnt);
    cudaGetSymbolAddress((void**)&wbt, g_wbt);
    cudaGetSymbolAddress((void**)&w1t, g_w1t);
    cudaGetSymbolAddress((void**)&w2t, g_w2t);

    cudaFuncSetAttribute(mm_mma_kernel, cudaFuncAttributeMaxDynamicSharedMemorySize, MM_SMEM);

    const int WARP_BLOCKS = NN / 8;
    const dim3 MMGRID((NN + 127) / 128, 2);   // 313 x 2

    // 0: big weight prep (coalesced transpose, fp16)
    wprep_kernel<<<dim3(KPBIG / 32, 8), 256>>>(W_in, wbt, KBIG, KPBIG);
    // 1-2: degree
    deg_init_kernel<<<(NN + 255) / 256, 256>>>(deg);
    deg_count_kernel<<<(EE + 255) / 256, 256>>>(ei, deg);
    // 3: BIG GEMM  <- ncu captures launch index 3
    mm_mma_kernel<<<MMGRID, 512, MM_SMEM>>>(x, wbt, b_in, x0, NN, KBIG, KPBIG);
    // 4-6: scan (coalesced, multi-block)
    scan_sum_kernel<<<SCB, 256>>>(deg, bsum);
    scan_top_kernel<<<1, 256>>>(bsum, off);
    scan_final_kernel<<<SCB, 256>>>(deg, bsum, off, pos);
    // 7: csr fill
    csr_fill_kernel<<<(ETOT + 255) / 256, 256>>>(ei, pos, csr);
    // conv weight preps
    wprep_kernel<<<dim3(256 / 32, 8), 256>>>(W1, w1t, 256, 256);
    wprep_kernel<<<dim3(256 / 32, 8), 256>>>(W2, w2t, 256, 256);

    // conv1
    mm_mma_kernel<<<MMGRID, 512, MM_SMEM>>>(x0, w1t, nullptr, h, NN, 256, 256);
    scores_kernel<8, 32><<<WARP_BLOCKS, 256>>>(h, as1, ad1, ssrc, sdst);
    agg_fused_kernel<8, 32, false><<<WARP_BLOCKS, 256>>>(
        ssrc, sdst, h, off, csr, b1, x0, g1, be1, x1,
        nullptr, nullptr, nullptr, nullptr, nullptr);

    // conv2 (+ fused pooling)
    mm_mma_kernel<<<MMGRID, 512, MM_SMEM>>>(x1, w2t, nullptr, h, NN, 256, 256);
    scores_kernel<4, 64><<<WARP_BLOCKS, 256>>>(h, as2, ad2, ssrc, sdst);
    pool_init_kernel<<<64, 256>>>(p2, p0, cnt);
    agg_fused_kernel<4, 64, true><<<WARP_BLOCKS, 256>>>(
        ssrc, sdst, h, off, csr, b2, x1, g2, be2, nullptr,
        x0, batch, p2, p0, cnt);

    // head
    head_kernel<<<BB, 256>>>(p2, p0, cnt, Wf, bfv, Wc1, bc1, Wc2, bc2, out);
}

// round 16
// speedup vs baseline: 2.5634x; 1.0625x over previous
#include <cuda_runtime.h>
#include <cuda_fp16.h>
#include <math.h>
#include <cstdint>

#define NN 40000
#define EE 1280000
#define ETOT (EE + NN)
#define DD 256
#define BB 64
#define NCLS 20
#define KBIG 5000
#define KPBIG 5056   /* 79 * 64 */
#define SCB 157      /* ceil(NN/256) scan blocks */

// ---------------- scratch (static device allocations) ----------------------
__device__ float g_x0[NN * DD];
__device__ float g_x1[NN * DD];
__device__ float g_h[NN * DD];
__device__ float g_ssrc[NN * 8];
__device__ float g_sdst[NN * 8];
__device__ int   g_deg[NN];
__device__ int   g_off[NN + 1];
__device__ int   g_pos[NN];
__device__ int   g_csr[ETOT];
__device__ int   g_bsum[256];
__device__ float g_p2[BB * DD];
__device__ float g_p0[BB * DD];
__device__ float g_cnt[BB];
__device__ __half g_xh[(size_t)NN * KPBIG];
__device__ __half g_wbt[256 * KPBIG];
__device__ __half g_w1t[256 * 256];
__device__ __half g_w2t[256 * 256];

__device__ __forceinline__ uint32_t smem_to_u32(const void* p) {
    uint32_t a;
    asm("{ .reg .u64 t; cvta.to.shared.u64 t, %1; cvt.u32.u64 %0, t; }"
        : "=r"(a) : "l"(p));
    return a;
}

__device__ __forceinline__ uint32_t h2pack(float a, float b) {
    __half2 t;
    t.x = __float2half_rn(a);
    t.y = __float2half_rn(b);
    return *reinterpret_cast<uint32_t*>(&t);
}

__device__ __forceinline__ void mma16816(float* c, const uint32_t* a, const uint32_t* b) {
    asm volatile(
        "mma.sync.aligned.m16n8k16.row.col.f32.f16.f16.f32 "
        "{%0,%1,%2,%3}, {%4,%5,%6,%7}, {%8,%9}, {%0,%1,%2,%3};"
        : "+f"(c[0]), "+f"(c[1]), "+f"(c[2]), "+f"(c[3])
        : "r"(a[0]), "r"(a[1]), "r"(a[2]), "r"(a[3]), "r"(b[0]), "r"(b[1]));
}

__device__ __forceinline__ void ldsm4(uint32_t* r, uint32_t addr) {
    asm volatile("ldmatrix.sync.aligned.m8n8.x4.shared.b16 {%0,%1,%2,%3}, [%4];"
        : "=r"(r[0]), "=r"(r[1]), "=r"(r[2]), "=r"(r[3]) : "r"(addr));
}

__device__ __forceinline__ void cpa16z(uint32_t sa, const void* g, int sz) {
    asm volatile("cp.async.cg.shared.global [%0], [%1], 16, %2;"
                 :: "r"(sa), "l"(g), "r"(sz));
}
__device__ __forceinline__ void cpa16(uint32_t sa, const void* g) {
    asm volatile("cp.async.cg.shared.global [%0], [%1], 16;" :: "r"(sa), "l"(g));
}
#define CP_COMMIT() asm volatile("cp.async.commit_group;" ::: "memory")

// ------- weight prep (coalesced transpose): W[K,256] -> Wt[256,KP] fp16 -----
__global__ void wprep_kernel(const float* __restrict__ W,
                             __half* __restrict__ th, int K, int KP)
{
    __shared__ float tile[32][33];
    const int kb = blockIdx.x * 32, nb = blockIdx.y * 32;
    const int tx = threadIdx.x & 31, ty = threadIdx.x >> 5;
#pragma unroll
    for (int r = ty; r < 32; r += 8) {
        int k = kb + r;
        tile[r][tx] = (k < K) ? __ldg(&W[(size_t)k * 256 + nb + tx]) : 0.f;
    }
    __syncthreads();
#pragma unroll
    for (int r = ty; r < 32; r += 8) {
        int n = nb + r, k = kb + tx;
        th[(size_t)n * KP + k] = __float2half_rn(tile[tx][r]);
    }
}

// ------- A prep: x[NN,KBIG] fp32 -> xh[NN,KPBIG] fp16 (zero-padded) --------
__global__ void aprep_kernel(const float* __restrict__ x, __half* __restrict__ xh)
{
    size_t idx = (size_t)blockIdx.x * 256 + threadIdx.x;   // over NN * KPBIG/8
    int row = (int)(idx / (KPBIG / 8));
    int c8  = (int)(idx % (KPBIG / 8)) * 8;
    if (row >= NN) return;
    uint4 o;
    if (c8 + 8 <= KBIG) {
        const float4* p = (const float4*)(x + (size_t)row * KBIG + c8);
        float4 v0 = p[0], v1 = p[1];
        o.x = h2pack(v0.x, v0.y);
        o.y = h2pack(v0.z, v0.w);
        o.z = h2pack(v1.x, v1.y);
        o.w = h2pack(v1.z, v1.w);
    } else {
        o = make_uint4(0, 0, 0, 0);   // pad region (KBIG % 8 == 0)
    }
    *(uint4*)(xh + (size_t)row * KPBIG + c8) = o;
}

// ---------------- shared GEMM layout constants -----------------------------
#define KROWB 80
#define ABUF_H 0
#define BBUF_H 10240
#define SUBSZ  20480
#define BUFSZ  (2 * SUBSZ)      /* 40960 */
#define MM_SMEM (2 * BUFSZ)     /* 81920 */

// -- mm_big: A fp16 + B fp16 both via cp.async, full double-buffer pipeline --
__global__ void __launch_bounds__(512, 1)
mm_big_kernel(const __half* __restrict__ Ah, const __half* __restrict__ Bh,
              const float* __restrict__ bias, float* __restrict__ C,
              int M, int KP)
{
    extern __shared__ char smem[];
    const uint32_t sb = smem_to_u32(smem);
    const int tid = threadIdx.x, wid = tid >> 5, lane = tid & 31;
    const int group = lane >> 2, tig = lane & 3;
    const int rg = wid >> 2, cg = wid & 3;
    const int r0 = blockIdx.x * 128, n0 = blockIdx.y * 128;

    float acc[2][4][4];
#pragma unroll
    for (int mt = 0; mt < 2; mt++)
#pragma unroll
        for (int nt = 0; nt < 4; nt++)
#pragma unroll
            for (int j = 0; j < 4; j++) acc[mt][nt][j] = 0.f;

    const int NCH = KP >> 6;

    // segment mapping for cp.async: idx = tid*2+q; r = idx>>3, s = idx&7
    const int i0 = tid * 2;
    const int sr0 = i0 >> 3, ss0 = i0 & 7;
    const int sr1 = (i0 + 1) >> 3, ss1 = (i0 + 1) & 7;
    const uint32_t dA0 = (uint32_t)(ss0 >> 2) * SUBSZ + ABUF_H + sr0 * KROWB + (ss0 & 3) * 16;
    const uint32_t dA1 = (uint32_t)(ss1 >> 2) * SUBSZ + ABUF_H + sr1 * KROWB + (ss1 & 3) * 16;
    const uint32_t dB0 = (uint32_t)(ss0 >> 2) * SUBSZ + BBUF_H + sr0 * KROWB + (ss0 & 3) * 16;
    const uint32_t dB1 = (uint32_t)(ss1 >> 2) * SUBSZ + BBUF_H + sr1 * KROWB + (ss1 & 3) * 16;
    const int azA0 = (r0 + sr0 < M) ? 16 : 0;
    const int azA1 = (r0 + sr1 < M) ? 16 : 0;
    const __half* A0 = Ah + (size_t)(r0 + sr0) * KP + ss0 * 8;
    const __half* A1 = Ah + (size_t)(r0 + sr1) * KP + ss1 * 8;
    const __half* B0 = Bh + (size_t)(n0 + sr0) * KP + ss0 * 8;
    const __half* B1 = Bh + (size_t)(n0 + sr1) * KP + ss1 * 8;

#define PREF(K0, BO) do {                                                    \
    cpa16z(sb + (BO) + dA0, A0 + (K0), azA0);                                \
    cpa16z(sb + (BO) + dA1, A1 + (K0), azA1);                                \
    cpa16(sb + (BO) + dB0, B0 + (K0));                                       \
    cpa16(sb + (BO) + dB1, B1 + (K0));                                       \
    CP_COMMIT();                                                             \
} while (0)

    // ldmatrix per-lane base offsets (same layout as before)
    const uint32_t a_lm = (uint32_t)(rg * 32 + (lane & 15)) * KROWB + (lane >> 4) * 16;
    const int bmat = lane >> 3, brow = lane & 7;
    const uint32_t b_lm = (uint32_t)(cg * 32 + (bmat & 1) * 8 + brow) * KROWB + (bmat >> 1) * 16;

    PREF(0, 0);

    for (int i = 0; i < NCH; i++) {
        const uint32_t bufa = sb + (uint32_t)(i & 1) * BUFSZ;
        if (i + 1 < NCH) {
            PREF((i + 1) << 6, ((i + 1) & 1) * BUFSZ);
            asm volatile("cp.async.wait_group 1;" ::: "memory");
        } else {
            asm volatile("cp.async.wait_group 0;" ::: "memory");
        }
        __syncthreads();

#pragma unroll
        for (int sub = 0; sub < 2; sub++) {
            const uint32_t bs = bufa + sub * SUBSZ;
#pragma unroll
            for (int ks = 0; ks < 2; ks++) {
                const uint32_t kb = (uint32_t)ks * 32;
                uint32_t ah[2][4], bhf[4][2];
#pragma unroll
                for (int mt = 0; mt < 2; mt++)
                    ldsm4(ah[mt], bs + ABUF_H + a_lm + mt * 16 * KROWB + kb);
#pragma unroll
                for (int ntp = 0; ntp < 2; ntp++) {
                    uint32_t r[4];
                    ldsm4(r, bs + BBUF_H + b_lm + ntp * 16 * KROWB + kb);
                    bhf[2*ntp][0] = r[0]; bhf[2*ntp+1][0] = r[1];
                    bhf[2*ntp][1] = r[2]; bhf[2*ntp+1][1] = r[3];
                }
#pragma unroll
                for (int mt = 0; mt < 2; mt++)
#pragma unroll
                    for (int nt = 0; nt < 4; nt++)
                        mma16816(acc[mt][nt], ah[mt], bhf[nt]);
            }
        }
        __syncthreads();
    }

    // ---- epilogue ----
#pragma unroll
    for (int nt = 0; nt < 4; nt++) {
        int c = n0 + cg * 32 + nt * 8 + tig * 2;
        float b0v = bias ? __ldg(bias + c) : 0.f;
        float b1v = bias ? __ldg(bias + c + 1) : 0.f;
#pragma unroll
        for (int mt = 0; mt < 2; mt++) {
            int r = r0 + rg * 32 + mt * 16 + group;
            if (r < M)
                *(float2*)(C + (size_t)r * 256 + c) =
                    make_float2(acc[mt][nt][0] + b0v, acc[mt][nt][1] + b1v);
            if (r + 8 < M)
                *(float2*)(C + (size_t)(r + 8) * 256 + c) =
                    make_float2(acc[mt][nt][2] + b0v, acc[mt][nt][3] + b1v);
        }
    }
#undef PREF
}

// -- mm_small: R14-proven fp32-A convert path (for the 256-K conv GEMMs) ----
__global__ void __launch_bounds__(512, 1)
mm_mma_kernel(const float* __restrict__ A,
              const __half* __restrict__ Bh,
              const float* __restrict__ bias,
              float* __restrict__ C, int M, int Kdim, int KP)
{
    extern __shared__ char smem[];
    const uint32_t sb = smem_to_u32(smem);
    const int tid = threadIdx.x, wid = tid >> 5, lane = tid & 31;
    const int group = lane >> 2, tig = lane & 3;
    const int rg = wid >> 2, cg = wid & 3;
    const int r0 = blockIdx.x * 128, n0 = blockIdx.y * 128;

    float acc[2][4][4];
#pragma unroll
    for (int mt = 0; mt < 2; mt++)
#pragma unroll
        for (int nt = 0; nt < 4; nt++)
#pragma unroll
            for (int j = 0; j < 4; j++) acc[mt][nt][j] = 0.f;

    const int NCH = KP >> 6;
    const int arow = tid >> 2;
    const int acol0 = (tid & 3) * 16;
    const bool arok = (r0 + arow) < M;
    const float* Abase = A + (size_t)(r0 + arow) * Kdim;
    const int bn = tid >> 2, bseg = tid & 3;

    float apf[16];
    uint4 bpfh[2];

#define LDG_CHUNK(K0) do {                                                   \
    _Pragma("unroll")                                                        \
    for (int ii = 0; ii < 4; ii++) {                                         \
        int c = (K0) + acol0 + ii * 4;                                       \
        float4 v = make_float4(0.f, 0.f, 0.f, 0.f);                          \
        if (arok) {                                                          \
            if (c + 3 < Kdim) v = *(const float4*)(Abase + c);               \
            else {                                                           \
                if (c     < Kdim) v.x = Abase[c];                            \
                if (c + 1 < Kdim) v.y = Abase[c + 1];                        \
                if (c + 2 < Kdim) v.z = Abase[c + 2];                        \
                if (c + 3 < Kdim) v.w = Abase[c + 3];                        \
            }                                                                \
        }                                                                    \
        apf[ii*4+0] = v.x; apf[ii*4+1] = v.y;                                \
        apf[ii*4+2] = v.z; apf[ii*4+3] = v.w;                                \
    }                                                                        \
    {                                                                        \
        size_t so = (size_t)(n0 + bn) * KP + (K0) + bseg * 16;               \
        bpfh[0] = *(const uint4*)(Bh + so);                                  \
        bpfh[1] = *(const uint4*)(Bh + so + 8);                              \
    }                                                                        \
} while (0)

    LDG_CHUNK(0);

    const uint32_t a_lm = (uint32_t)(rg * 32 + (lane & 15)) * KROWB + (lane >> 4) * 16;
    const int bmat = lane >> 3, brow = lane & 7;
    const uint32_t b_lm = (uint32_t)(cg * 32 + (bmat & 1) * 8 + brow) * KROWB + (bmat >> 1) * 16;

    for (int i = 0; i < NCH; i++) {
        char* buf = smem + (size_t)(i & 1) * BUFSZ;
        const uint32_t bufa = sb + (uint32_t)(i & 1) * BUFSZ;

        {
            uint32_t ph[8];
#pragma unroll
            for (int j = 0; j < 8; j++)
                ph[j] = h2pack(apf[2 * j], apf[2 * j + 1]);
            int asub = acol0 >> 5;
            int kloc = acol0 & 31;
            char* ab = buf + asub * SUBSZ + arow * KROWB + kloc * 2;
            *(uint4*)(ab + ABUF_H)      = make_uint4(ph[0], ph[1], ph[2], ph[3]);
            *(uint4*)(ab + ABUF_H + 16) = make_uint4(ph[4], ph[5], ph[6], ph[7]);
            int bsub = bseg >> 1;
            int bkloc = (bseg & 1) * 16;
            char* bb = buf + bsub * SUBSZ + bn * KROWB + bkloc * 2;
            *(uint4*)(bb + BBUF_H)      = bpfh[0];
            *(uint4*)(bb + BBUF_H + 16) = bpfh[1];
        }
        __syncthreads();

        if (i + 1 < NCH) LDG_CHUNK((i + 1) << 6);

#pragma unroll
        for (int sub = 0; sub < 2; sub++) {
            const uint32_t bs = bufa + sub * SUBSZ;
#pragma unroll
            for (int ks = 0; ks < 2; ks++) {
                const uint32_t kb = (uint32_t)ks * 32;
                uint32_t ah[2][4], bhf[4][2];
#pragma unroll
                for (int mt = 0; mt < 2; mt++)
                    ldsm4(ah[mt], bs + ABUF_H + a_lm + mt * 16 * KROWB + kb);
#pragma unroll
                for (int ntp = 0; ntp < 2; ntp++) {
                    uint32_t r[4];
                    ldsm4(r, bs + BBUF_H + b_lm + ntp * 16 * KROWB + kb);
                    bhf[2*ntp][0] = r[0]; bhf[2*ntp+1][0] = r[1];
                    bhf[2*ntp][1] = r[2]; bhf[2*ntp+1][1] = r[3];
                }
#pragma unroll
                for (int mt = 0; mt < 2; mt++)
#pragma unroll
                    for (int nt = 0; nt < 4; nt++)
                        mma16816(acc[mt][nt], ah[mt], bhf[nt]);
            }
        }
    }

#pragma unroll
    for (int nt = 0; nt < 4; nt++) {
        int c = n0 + cg * 32 + nt * 8 + tig * 2;
        float b0v = bias ? __ldg(bias + c) : 0.f;
        float b1v = bias ? __ldg(bias + c + 1) : 0.f;
#pragma unroll
        for (int mt = 0; mt < 2; mt++) {
            int r = r0 + rg * 32 + mt * 16 + group;
            if (r < M)
                *(float2*)(C + (size_t)r * 256 + c) =
                    make_float2(acc[mt][nt][0] + b0v, acc[mt][nt][1] + b1v);
            if (r + 8 < M)
                *(float2*)(C + (size_t)(r + 8) * 256 + c) =
                    make_float2(acc[mt][nt][2] + b0v, acc[mt][nt][3] + b1v);
        }
    }
#undef LDG_CHUNK
}

// ---------------- CSR build ------------------------------------------------
__global__ void deg_init_kernel(int* deg) {
    int i = blockIdx.x * blockDim.x + threadIdx.x;
    if (i < NN) deg[i] = 1;
}
__global__ void deg_count_kernel(const int* __restrict__ ei, int* deg) {
    int i = blockIdx.x * blockDim.x + threadIdx.x;
    if (i < EE) atomicAdd(&deg[ei[EE + i]], 1);
}

// --- 3-kernel coalesced scan ---
__global__ void scan_sum_kernel(const int* __restrict__ deg, int* __restrict__ bsum) {
    int i = blockIdx.x * 256 + threadIdx.x;
    int lane = threadIdx.x & 31, wid = threadIdx.x >> 5;
    int d = (i < NN) ? deg[i] : 0;
#pragma unroll
    for (int o = 16; o > 0; o >>= 1) d += __shfl_xor_sync(0xffffffffu, d, o);
    __shared__ int ws[8];
    if (lane == 0) ws[wid] = d;
    __syncthreads();
    if (threadIdx.x == 0) {
        int s = 0;
#pragma unroll
        for (int w = 0; w < 8; w++) s += ws[w];
        bsum[blockIdx.x] = s;
    }
}
__global__ void scan_top_kernel(int* __restrict__ bsum, int* __restrict__ off) {
    int t = threadIdx.x, lane = t & 31, wid = t >> 5;
    int v = (t < SCB) ? bsum[t] : 0;
    int x = v;
#pragma unroll
    for (int o = 1; o < 32; o <<= 1) {
        int y = __shfl_up_sync(0xffffffffu, x, o);
        if (lane >= o) x += y;
    }
    __shared__ int ws[8];
    if (lane == 31) ws[wid] = x;
    __syncthreads();
    int wpre = 0;
#pragma unroll
    for (int w = 0; w < 8; w++) if (w < wid) wpre += ws[w];
    int incl = x + wpre;
    if (t < SCB) bsum[t] = incl - v;
    if (t == 255) off[NN] = incl;
}
__global__ void scan_final_kernel(const int* __restrict__ deg,
                                  const int* __restrict__ bsum,
                                  int* __restrict__ off, int* __restrict__ pos) {
    int i = blockIdx.x * 256 + threadIdx.x;
    int lane = threadIdx.x & 31, wid = threadIdx.x >> 5;
    int d = (i < NN) ? deg[i] : 0;
    int x = d;
#pragma unroll
    for (int o = 1; o < 32; o <<= 1) {
        int y = __shfl_up_sync(0xffffffffu, x, o);
        if (lane >= o) x += y;
    }
    __shared__ int ws[8];
    if (lane == 31) ws[wid] = x;
    __syncthreads();
    int wpre = 0;
#pragma unroll
    for (int w = 0; w < 8; w++) if (w < wid) wpre += ws[w];
    int excl = x - d + wpre + bsum[blockIdx.x];
    if (i < NN) { off[i] = excl; pos[i] = excl; }
}

__global__ void csr_fill_kernel(const int* __restrict__ ei, int* pos, int* csr) {
    int i = blockIdx.x * blockDim.x + threadIdx.x;
    if (i >= ETOT) return;
    int s, d;
    if (i < EE) { s = ei[i]; d = ei[EE + i]; }
    else        { s = d = i - EE; }
    int p = atomicAdd(&pos[d], 1);
    csr[p] = s;
}

// ---------------- attention scores ----------------------------------------
template <int H, int C>
__global__ void scores_kernel(const float* __restrict__ h,
                              const float* __restrict__ asrc,
                              const float* __restrict__ adst,
                              float* __restrict__ ssrc, float* __restrict__ sdst)
{
    int gw = (blockIdx.x * blockDim.x + threadIdx.x) >> 5;
    if (gw >= NN) return;
    int lane = threadIdx.x & 31;

    const float4* hp = (const float4*)(h + gw * 256 + lane * 8);
    float4 v0 = hp[0], v1 = hp[1];
    const float4* ap = (const float4*)(asrc + lane * 8);
    float4 a0 = ap[0], a1 = ap[1];
    const float4* dp = (const float4*)(adst + lane * 8);
    float4 d0 = dp[0], d1 = dp[1];

    float ps = v0.x * a0.x + v0.y * a0.y + v0.z * a0.z + v0.w * a0.w +
               v1.x * a1.x + v1.y * a1.y + v1.z * a1.z + v1.w * a1.w;
    float pd = v0.x * d0.x + v0.y * d0.y + v0.z * d0.z + v0.w * d0.w +
               v1.x * d1.x + v1.y * d1.y + v1.z * d1.z + v1.w * d1.w;

    const int GC = C / 8;
#pragma unroll
    for (int o = 1; o < GC; o <<= 1) {
        ps += __shfl_xor_sync(0xffffffffu, ps, o);
        pd += __shfl_xor_sync(0xffffffffu, pd, o);
    }
    int myh = lane / GC;
    if ((lane & (GC - 1)) == 0) {
        ssrc[gw * H + myh] = ps;
        sdst[gw * H + myh] = pd;
    }
}

// ------- GAT aggregation fused with bias+elu+residual+LN (+ pooling) -------
template <int H, int C, bool POOL>
__global__ void agg_fused_kernel(const float* __restrict__ ssrc,
                                 const float* __restrict__ sdst,
                                 const float* __restrict__ h,
                                 const int* __restrict__ off,
                                 const int* __restrict__ csr,
                                 const float* __restrict__ bias,
                                 const float* __restrict__ xin,
                                 const float* __restrict__ g,
                                 const float* __restrict__ be,
                                 float* __restrict__ xout,
                                 const float* __restrict__ x0p,
                                 const int* __restrict__ batch,
                                 float* __restrict__ p2,
                                 float* __restrict__ p0,
                                 float* __restrict__ cnt)
{
    int gw = (blockIdx.x * blockDim.x + threadIdx.x) >> 5;
    if (gw >= NN) return;
    int lane = threadIdx.x & 31;

    int e0 = off[gw];
    int deg = off[gw + 1] - e0;

    const int ES = 32 / H;
    int hh = lane % H;
    int j0 = lane / H;

    float sd = __ldg(&sdst[gw * H + hh]);
    float m = -1e30f, z = 0.f;
    for (int j = j0; j < deg; j += ES) {
        int s = __ldg(&csr[e0 + j]);
        float e = __ldg(&ssrc[s * H + hh]) + sd;
        e = e > 0.f ? e : 0.2f * e;
        float mn = fmaxf(m, e);
        z = z * __expf(m - mn) + __expf(e - mn);
        m = mn;
    }
#pragma unroll
    for (int o = H; o < 32; o <<= 1) {
        float mo = __shfl_xor_sync(0xffffffffu, m, o);
        float zo = __shfl_xor_sync(0xffffffffu, z, o);
        float mn = fmaxf(m, mo);
        z = z * __expf(m - mn) + zo * __expf(mo - mn);
        m = mn;
    }

    const int myh = (lane * 8) / C;
    float my_m  = __shfl_sync(0xffffffffu, m, myh);
    float my_zi = 1.f / __shfl_sync(0xffffffffu, z, myh);
    float my_sd = __ldg(&sdst[gw * H + myh]);

    float acc[8] = {0.f, 0.f, 0.f, 0.f, 0.f, 0.f, 0.f, 0.f};
    for (int j = 0; j < deg; j++) {
        int s = __ldg(&csr[e0 + j]);
        float e = __ldg(&ssrc[s * H + myh]) + my_sd;
        e = e > 0.f ? e : 0.2f * e;
        float a = __expf(e - my_m) * my_zi;
        const float4* hp = (const float4*)(h + s * 256 + lane * 8);
        float4 v0 = __ldg(hp);
        float4 v1 = __ldg(hp + 1);
        acc[0] += a * v0.x; acc[1] += a * v0.y; acc[2] += a * v0.z; acc[3] += a * v0.w;
        acc[4] += a * v1.x; acc[5] += a * v1.y; acc[6] += a * v1.z; acc[7] += a * v1.w;
    }

    int base = gw * 256 + lane * 8;
    float4 b0 = *(const float4*)(bias + lane * 8);
    float4 b1 = *(const float4*)(bias + lane * 8 + 4);
    float4 x0v = *(const float4*)(xin + base);
    float4 x1v = *(const float4*)(xin + base + 4);
    float bb[8] = {b0.x, b0.y, b0.z, b0.w, b1.x, b1.y, b1.z, b1.w};
    float xv[8] = {x0v.x, x0v.y, x0v.z, x0v.w, x1v.x, x1v.y, x1v.z, x1v.w};

    float v[8];
    float sum = 0.f, sq = 0.f;
#pragma unroll
    for (int k = 0; k < 8; k++) {
        float t = acc[k] + bb[k];
        t = (t > 0.f) ? t : (__expf(t) - 1.f);
        t += xv[k];
        v[k] = t;
        sum += t;
        sq += t * t;
    }
#pragma unroll
    for (int o = 1; o < 32; o <<= 1) {
        sum += __shfl_xor_sync(0xffffffffu, sum, o);
        sq  += __shfl_xor_sync(0xffffffffu, sq, o);
    }
    float mean = sum * (1.f / 256.f);
    float var  = sq * (1.f / 256.f) - mean * mean;
    float rs   = rsqrtf(var + 1e-5f);

    float4 g0 = *(const float4*)(g + lane * 8);
    float4 g1 = *(const float4*)(g + lane * 8 + 4);
    float4 e0v = *(const float4*)(be + lane * 8);
    float4 e1v = *(const float4*)(be + lane * 8 + 4);
    float gv[8] = {g0.x, g0.y, g0.z, g0.w, g1.x, g1.y, g1.z, g1.w};
    float ev[8] = {e0v.x, e0v.y, e0v.z, e0v.w, e1v.x, e1v.y, e1v.z, e1v.w};

    float o0[8];
#pragma unroll
    for (int k = 0; k < 8; k++) o0[k] = (v[k] - mean) * rs * gv[k] + ev[k];

    if (!POOL) {
        *(float4*)(xout + base)     = make_float4(o0[0], o0[1], o0[2], o0[3]);
        *(float4*)(xout + base + 4) = make_float4(o0[4], o0[5], o0[6], o0[7]);
    } else {
        int b = __ldg(&batch[gw]);
        float* pp2 = p2 + b * 256 + lane * 8;
        float* pp0 = p0 + b * 256 + lane * 8;
        float4 z0 = *(const float4*)(x0p + base);
        float4 z1 = *(const float4*)(x0p + base + 4);
        float zv[8] = {z0.x, z0.y, z0.z, z0.w, z1.x, z1.y, z1.z, z1.w};
#pragma unroll
        for (int k = 0; k < 8; k++) {
            atomicAdd(pp2 + k, o0[k]);
            atomicAdd(pp0 + k, zv[k]);
        }
        if (lane == 0) atomicAdd(&cnt[b], 1.f);
    }
}

// ---------------- pooling init ---------------------------------------------
__global__ void pool_init_kernel(float* p2, float* p0, float* cnt) {
    int i = blockIdx.x * blockDim.x + threadIdx.x;
    if (i < BB * DD) { p2[i] = 0.f; p0[i] = 0.f; }
    if (i < BB) cnt[i] = 0.f;
}

// ---------------- classification head (block per graph) -------------------
__global__ void head_kernel(const float* __restrict__ p2,
                            const float* __restrict__ p0,
                            const float* __restrict__ cnt,
                            const float* __restrict__ Wf,  const float* __restrict__ bf,
                            const float* __restrict__ Wc1, const float* __restrict__ bc1,
                            const float* __restrict__ Wc2, const float* __restrict__ bc2,
                            float* __restrict__ out)
{
    __shared__ float xc[512];
    __shared__ float f[256];
    __shared__ float c1[128];
    __shared__ float lg[20];

    int b = blockIdx.x, t = threadIdx.x;
    float c = fmaxf(cnt[b], 1.f);
    xc[t]       = p2[b * 256 + t] / c;
    xc[256 + t] = p0[b * 256 + t] / c;
    __syncthreads();

    float acc = bf[t];
    for (int i = 0; i < 512; i++) acc += xc[i] * Wf[i * 256 + t];
    f[t] = fmaxf(acc, 0.f);
    __syncthreads();

    if (t < 128) {
        float a = bc1[t];
        for (int i = 0; i < 256; i++) a += f[i] * Wc1[i * 128 + t];
        c1[t] = fmaxf(a, 0.f);
    }
    __syncthreads();

    if (t < 20) {
        float a = bc2[t];
        for (int i = 0; i < 128; i++) a += c1[i] * Wc2[i * 20 + t];
        lg[t] = a;
    }
    __syncthreads();

    if (t < 32) {
        float v = (t < 20) ? lg[t] : -1e30f;
        float m = v;
#pragma unroll
        for (int o = 1; o < 32; o <<= 1) m = fmaxf(m, __shfl_xor_sync(0xffffffffu, m, o));
        float e = (t < 20) ? expf(v - m) : 0.f;
        float s = e;
#pragma unroll
        for (int o = 1; o < 32; o <<= 1) s += __shfl_xor_sync(0xffffffffu, s, o);
        if (t < 20) out[b * 20 + t] = v - m - logf(s);
    }
}

// ---------------- launcher -------------------------------------------------
extern "C" void kernel_launch(void* const* d_in, const int* in_sizes, int n_in,
                              void* d_out, int out_size)
{
    const float* x    = (const float*)d_in[0];
    const int*   ei   = (const int*)  d_in[1];
    const int*   batch= (const int*)  d_in[2];
    const float* W_in = (const float*)d_in[3];
    const float* b_in = (const float*)d_in[4];
    const float* W1   = (const float*)d_in[5];
    const float* as1  = (const float*)d_in[6];
    const float* ad1  = (const float*)d_in[7];
    const float* b1   = (const float*)d_in[8];
    const float* g1   = (const float*)d_in[9];
    const float* be1  = (const float*)d_in[10];
    const float* W2   = (const float*)d_in[11];
    const float* as2  = (const float*)d_in[12];
    const float* ad2  = (const float*)d_in[13];
    const float* b2   = (const float*)d_in[14];
    const float* g2   = (const float*)d_in[15];
    const float* be2  = (const float*)d_in[16];
    const float* Wf   = (const float*)d_in[17];
    const float* bfv  = (const float*)d_in[18];
    const float* Wc1  = (const float*)d_in[19];
    const float* bc1  = (const float*)d_in[20];
    const float* Wc2  = (const float*)d_in[21];
    const float* bc2  = (const float*)d_in[22];
    float* out = (float*)d_out;

    float *x0, *x1, *h, *ssrc, *sdst, *p2, *p0, *cnt;
    int *deg, *off, *pos, *csr, *bsum;
    __half *xh, *wbt, *w1t, *w2t;
    cudaGetSymbolAddress((void**)&x0,  g_x0);
    cudaGetSymbolAddress((void**)&x1,  g_x1);
    cudaGetSymbolAddress((void**)&h,   g_h);
    cudaGetSymbolAddress((void**)&ssrc,g_ssrc);
    cudaGetSymbolAddress((void**)&sdst,g_sdst);
    cudaGetSymbolAddress((void**)&deg, g_deg);
    cudaGetSymbolAddress((void**)&off, g_off);
    cudaGetSymbolAddress((void**)&pos, g_pos);
    cudaGetSymbolAddress((void**)&csr, g_csr);
    cudaGetSymbolAddress((void**)&bsum,g_bsum);
    cudaGetSymbolAddress((void**)&p2,  g_p2);
    cudaGetSymbolAddress((void**)&p0,  g_p0);
    cudaGetSymbolAddress((void**)&cnt, g_cnt);
    cudaGetSymbolAddress((void**)&xh,  g_xh);
    cudaGetSymbolAddress((void**)&wbt, g_wbt);
    cudaGetSymbolAddress((void**)&w1t, g_w1t);
    cudaGetSymbolAddress((void**)&w2t, g_w2t);

    cudaFuncSetAttribute(mm_big_kernel, cudaFuncAttributeMaxDynamicSharedMemorySize, MM_SMEM);
    cudaFuncSetAttribute(mm_mma_kernel, cudaFuncAttributeMaxDynamicSharedMemorySize, MM_SMEM);

    const int WARP_BLOCKS = NN / 8;
    const dim3 MMGRID((NN + 127) / 128, 2);   // 313 x 2

    // 0: big weight prep
    wprep_kernel<<<dim3(KPBIG / 32, 8), 256>>>(W_in, wbt, KBIG, KPBIG);
    // 1: A prep (fp32 -> fp16 padded)
    aprep_kernel<<<(int)(((size_t)NN * KPBIG / 8 + 255) / 256), 256>>>(x, xh);
    // 2: degree init
    deg_init_kernel<<<(NN + 255) / 256, 256>>>(deg);
    // 3: BIG GEMM  <- ncu captures launch index 3
    mm_big_kernel<<<MMGRID, 512, MM_SMEM>>>(xh, wbt, b_in, x0, NN, KPBIG);
    // 4: degree count
    deg_count_kernel<<<(EE + 255) / 256, 256>>>(ei, deg);
    // 5-7: scan
    scan_sum_kernel<<<SCB, 256>>>(deg, bsum);
    scan_top_kernel<<<1, 256>>>(bsum, off);
    scan_final_kernel<<<SCB, 256>>>(deg, bsum, off, pos);
    // 8: csr fill
    csr_fill_kernel<<<(ETOT + 255) / 256, 256>>>(ei, pos, csr);
    // conv weight preps
    wprep_kernel<<<dim3(256 / 32, 8), 256>>>(W1, w1t, 256, 256);
    wprep_kernel<<<dim3(256 / 32, 8), 256>>>(W2, w2t, 256, 256);

    // conv1
    mm_mma_kernel<<<MMGRID, 512, MM_SMEM>>>(x0, w1t, nullptr, h, NN, 256, 256);
    scores_kernel<8, 32><<<WARP_BLOCKS, 256>>>(h, as1, ad1, ssrc, sdst);
    agg_fused_kernel<8, 32, false><<<WARP_BLOCKS, 256>>>(
        ssrc, sdst, h, off, csr, b1, x0, g1, be1, x1,
        nullptr, nullptr, nullptr, nullptr, nullptr);

    // conv2 (+ fused pooling)
    mm_mma_kernel<<<MMGRID, 512, MM_SMEM>>>(x1, w2t, nullptr, h, NN, 256, 256);
    scores_kernel<4, 64><<<WARP_BLOCKS, 256>>>(h, as2, ad2, ssrc, sdst);
    pool_init_kernel<<<64, 256>>>(p2, p0, cnt);
    agg_fused_kernel<4, 64, true><<<WARP_BLOCKS, 256>>>(
        ssrc, sdst, h, off, csr, b2, x1, g2, be2, nullptr,
        x0, batch, p2, p0, cnt);

    // head
    head_kernel<<<BB, 256>>>(p2, p0, cnt, Wf, bfv, Wc1, bc1, Wc2, bc2, out);
}